// round 13
// baseline (speedup 1.0000x reference)
#include <cuda_runtime.h>
#include <math.h>

// ---------------------------------------------------------------------------
// S2ConvNet forward pass, sm_103a.
// Shapes: B=16, F1=32, F2=64, B0=32, B1=16, B2=8, M1=31, M2=15.
// ---------------------------------------------------------------------------

#define PI_D 3.141592653589793238462643383279502884
#define TWOPI_32F 0.19634954084936207f   // 2*pi/32

// ------------------------- static device scratch ---------------------------
__device__ float  g_D1F[16 * 64 * 31];                       // [l][j][m]
__device__ __align__(16) float g_D1I[16 * 32 * 31 * 32];     // [l][j][m][n] n padded
__device__ float  g_D2F[8 * 32 * 15 * 15];                   // [l][j][m][k]
__device__ float  g_D2I0[8 * 15 * 15];                       // [l][m][n]
__device__ float2 g_xh[16 * 16 * 31];                        // [b][l][m]
__device__ __align__(16) float2 g_xmn[16 * 32 * 32 * 225];   // [b][c][j][m][k]
__device__ __align__(16) float2 g_G[16 * 32 * 1800];         // [b][c][l][n][k]
__device__ float  g_partial[32 * 8 * 128];
__device__ unsigned int g_done = 0;     // last-block counter (reset each call)

__device__ static const double c_F[32] = {
    1.0, 1.0, 2.0, 6.0, 24.0, 120.0, 720.0, 5040.0, 40320.0, 362880.0,
    3628800.0, 39916800.0, 479001600.0, 6227020800.0, 87178291200.0,
    1307674368000.0, 20922789888000.0, 355687428096000.0, 6402373705728000.0,
    121645100408832000.0, 2432902008176640000.0, 51090942171709440000.0,
    1124000727777607680000.0, 25852016738884976640000.0,
    620448401733239439360000.0, 15511210043330985984000000.0,
    403291461126605635584000000.0, 10888869450418352160768000000.0,
    304888344611713860501504000000.0, 8841761993739701954543616000000.0,
    265252859812191058636308480000000.0, 8222838654177922817725562880000000.0
};

__device__ static const double c_R[32] = {
    0.0, 1.0, 1.0/2.0, 1.0/3.0, 1.0/4.0, 1.0/5.0, 1.0/6.0, 1.0/7.0,
    1.0/8.0, 1.0/9.0, 1.0/10.0, 1.0/11.0, 1.0/12.0, 1.0/13.0, 1.0/14.0,
    1.0/15.0, 1.0/16.0, 1.0/17.0, 1.0/18.0, 1.0/19.0, 1.0/20.0, 1.0/21.0,
    1.0/22.0, 1.0/23.0, 1.0/24.0, 1.0/25.0, 1.0/26.0, 1.0/27.0, 1.0/28.0,
    1.0/29.0, 1.0/30.0, 1.0/31.0
};

__device__ __forceinline__ double ipow_d(double x, int e) {
    double r = 1.0;
    while (e) { if (e & 1) r *= x; x *= x; e >>= 1; }
    return r;
}

__device__ double wig_fast(int l, int m, int n, double cb, double sb, double ts) {
    int kmin = max(0, m - n);
    int kmax = min(l + m, l - n);
    if (kmax < kmin) return 0.0;
    double t = sqrt(c_F[l + m] * c_F[l - m] * c_F[l + n] * c_F[l - n])
             / (c_F[kmin] * c_F[l + m - kmin] * c_F[l - n - kmin] * c_F[n - m + kmin]);
    t *= ipow_d(cb, 2 * l + m - n - 2 * kmin) * ipow_d(sb, n - m + 2 * kmin);
    if (kmin & 1) t = -t;
    double s = t;
    for (int k = kmin; k < kmax; ++k) {
        t *= -((double)((l + m - k) * (l - n - k)) *
               c_R[k + 1] * c_R[n - m + k + 1]) * ts;
        s += t;
    }
    return s;
}

// quadrature weight for bandwidth bq at angle beta (Chebyshev sine recurrence)
__device__ __forceinline__ double quad_w(int bq, double sb, double cb) {
    double sinb = 2.0 * sb * cb;
    double c2 = 1.0 - 2.0 * sinb * sinb;
    double prev = -sinb, cur = sinb, s = 0.0;
    for (int k = 0; k < bq; ++k) {
        s += cur * (1.0 / (2.0 * k + 1.0));
        double nx = 2.0 * c2 * cur - prev;
        prev = cur; cur = nx;
    }
    return (2.0 / (double)bq) * sinb * s;
}

// ------------------------- merged table kernel (trig inline) ---------------
// D1I: 4-fold symmetry (canonical wedge nt >= |mt|).
// D1F: mirror symmetry d_{-m,0} = (-1)^m d_{m,0}.
__global__ void t_tables() {
    int idx = blockIdx.x * blockDim.x + threadIdx.x;
    if (idx < 31744) {
        int l = idx / (64 * 31);
        int j = (idx / 31) % 64;
        int m = idx % 31;
        int mt = m - 15;
        float* base = g_D1F + (size_t)l * 64 * 31 + (size_t)j * 31;
        if (abs(mt) > l) { base[m] = 0.f; return; }
        if (mt < 0) return;
        double beta = PI_D * (2.0 * j + 1.0) / 128.0;
        double sb, cb;
        sincos(beta * 0.5, &sb, &cb);
        double ts = (sb * sb) / (cb * cb);
        double w0 = quad_w(32, sb, cb);
        float v = (float)(w0 * wig_fast(l, mt, 0, cb, sb, ts));
        base[m] = v;
        base[30 - m] = (mt & 1) ? -v : v;
        return;
    }
    idx -= 31744;
    if (idx < 507904) {
        int l = idx / 31744;
        int r = idx % 31744;
        int j = r / 992;
        int m = (r / 32) % 31;
        int n = r % 32;
        float* base = g_D1I + (size_t)l * 31744 + (size_t)j * 992;
        if (n == 31) { base[m * 32 + 31] = 0.f; return; }
        int mt = m - 15, nt = n - 15;
        if (abs(mt) > l || abs(nt) > l) { base[m * 32 + n] = 0.f; return; }
        if (nt < abs(mt)) return;
        double beta = PI_D * (2.0 * j + 1.0) / 64.0;
        double sb, cb;
        sincos(beta * 0.5, &sb, &cb);
        double ts = (sb * sb) / (cb * cb);
        float vf = (float)((2.0 * l + 1.0) * wig_fast(l, mt, nt, cb, sb, ts));
        float sv = ((m - n) & 1) ? -vf : vf;
        base[m * 32 + n] = vf;
        base[n * 32 + m] = sv;
        base[(30 - m) * 32 + (30 - n)] = sv;
        base[(30 - n) * 32 + (30 - m)] = vf;
        return;
    }
    idx -= 507904;
    if (idx < 57600) {
        int l = idx / (32 * 225);
        int j = (idx / 225) % 32;
        int m = (idx / 15) % 15;
        int n = idx % 15;
        int mt = m - 7, nt = n - 7;
        float v = 0.f;
        if (abs(mt) <= l && abs(nt) <= l) {
            double beta = PI_D * (2.0 * j + 1.0) / 64.0;
            double sb, cb;
            sincos(beta * 0.5, &sb, &cb);
            double ts = (sb * sb) / (cb * cb);
            double w1 = quad_w(16, sb, cb);
            v = (float)(w1 * wig_fast(l, mt, nt, cb, sb, ts));
        }
        g_D2F[idx] = v;
        return;
    }
    idx -= 57600;
    if (idx < 1800) {
        int l = idx / 225;
        int m = (idx / 15) % 15;
        int n = idx % 15;
        int mt = m - 7, nt = n - 7;
        float v = 0.f;
        if (abs(mt) <= l && abs(nt) <= l) {
            double beta = PI_D / 32.0;
            double sb, cb;
            sincos(beta * 0.5, &sb, &cb);
            double ts = (sb * sb) / (cb * cb);
            v = (float)((2.0 * l + 1.0) * wig_fast(l, mt, nt, cb, sb, ts));
        }
        g_D2I0[idx] = v;
    }
}

// ------------------------- stage A: x -> xh --------------------------------
__global__ void k_xh(const float* __restrict__ x) {
    __shared__ float2 s_tw[64];
    __shared__ float2 s_xm[64];
    int b = blockIdx.x / 31;
    int m = blockIdx.x % 31;
    int mt = m - 15;
    int j = threadIdx.x;   // 64

    float sj, cj;
    __sincosf((float)j * (6.2831853071795864769f / 64.f), &sj, &cj);
    s_tw[j] = make_float2(cj, sj);
    __syncthreads();

    const float* xr = x + (size_t)(b * 64 + j) * 64;
    float accx = 0.f, accy = 0.f;
#pragma unroll 8
    for (int t = 0; t < 64; ++t) {
        unsigned r = ((unsigned)(mt * t)) & 63u;
        float2 e = s_tw[r];
        float v = xr[t];
        accx += v * e.x;
        accy -= v * e.y;
    }
    s_xm[j] = make_float2(accx, accy);
    __syncthreads();

    if (j < 16) {
        int l = j;
        float ax = 0.f, ay = 0.f;
        const float* dp = g_D1F + (size_t)l * 64 * 31 + m;
#pragma unroll 8
        for (int jj = 0; jj < 64; ++jj) {
            float d = dp[jj * 31];
            float2 v = s_xm[jj];
            ax += d * v.x;
            ay += d * v.y;
        }
        g_xh[(b * 16 + l) * 31 + m] = make_float2(ax, ay);
    }
}

// ------------------------- stage B+C fused plane kernel (b-paired) ---------
__global__ __launch_bounds__(256, 3) void k_main(const float* __restrict__ w1r,
                                                 const float* __restrict__ w1i) {
    __shared__ float2 s_xh2[2 * 496];                  // 7.9 KB
    __shared__ __align__(16) float2 s_w1[16 * 32];     // 4 KB
    __shared__ __align__(16) float2 s_f2[2 * 1056];    // 16.9 KB
    __shared__ float2 s_g[31 * 32];                    // 7.9 KB
    __shared__ __align__(16) float4 s_p4[31 * 16];     // 7.9 KB
    __shared__ float  s_r016[64];

    float2* sp3 = (float2*)s_p4;

    int bx = blockIdx.x;
    int bp = bx >> 10;
    int f = (bx >> 5) & 31;
    int j = bx & 31;
    int tid = threadIdx.x;

    for (int i = tid; i < 992; i += 256)
        s_xh2[i] = g_xh[(2 * bp) * 496 + i];
    for (int i = tid; i < 496; i += 256) {
        int l = i / 31, n = i % 31;
        s_w1[l * 32 + n] = make_float2(w1r[f * 496 + i], w1i[f * 496 + i]);
    }
    if (tid < 16) s_w1[tid * 32 + 31] = make_float2(0.f, 0.f);
    __syncthreads();

    // step 1 (both planes)
    if (tid < 248) {
        int m = tid >> 3, ng = tid & 7, n0 = ng * 4;
        int am = abs(m - 15);
        int nhi = n0 + 3;
        int anmin = (nhi < 15) ? (15 - nhi) : ((n0 > 15) ? (n0 - 15) : 0);
        int l0 = max(am, anmin);
        float ax[2][4] = {{0.f, 0.f, 0.f, 0.f}, {0.f, 0.f, 0.f, 0.f}};
        float ay[2][4] = {{0.f, 0.f, 0.f, 0.f}, {0.f, 0.f, 0.f, 0.f}};
        const float4* dp4 = (const float4*)(g_D1I + (size_t)j * 992 + m * 32 + n0);
        for (int l = l0; l < 16; ++l) {
            float4 d = dp4[l * 7936];
            float2 aA = s_xh2[l * 31 + m];
            float2 aB = s_xh2[496 + l * 31 + m];
            float4 wA = *(const float4*)(s_w1 + l * 32 + n0);
            float4 wB = *(const float4*)(s_w1 + l * 32 + n0 + 2);
            float wx[4] = {wA.x, wA.z, wB.x, wB.z};
            float wy[4] = {wA.y, wA.w, wB.y, wB.w};
            float dv[4] = {d.x, d.y, d.z, d.w};
#pragma unroll
            for (int k = 0; k < 4; ++k) {
                float tr = aA.x * wx[k] + aA.y * wy[k];
                float ti = aA.y * wx[k] - aA.x * wy[k];
                ax[0][k] += dv[k] * tr; ay[0][k] += dv[k] * ti;
                tr = aB.x * wx[k] + aB.y * wy[k];
                ti = aB.y * wx[k] - aB.x * wy[k];
                ax[1][k] += dv[k] * tr; ay[1][k] += dv[k] * ti;
            }
        }
#pragma unroll
        for (int bb = 0; bb < 2; ++bb) {
            float2* sf = s_f2 + bb * 1056;
            *(float4*)(sf + m * 34 + n0)     = make_float4(ax[bb][0], ay[bb][0], ax[bb][1], ay[bb][1]);
            *(float4*)(sf + m * 34 + n0 + 2) = make_float4(ax[bb][2], ay[bb][2], ax[bb][3], ay[bb][3]);
        }
    }
    __syncthreads();

    for (int bb = 0; bb < 2; ++bb) {
        float2* s_f = s_f2 + bb * 1056;
        float2* sp4 = s_f;
        float2* s_u = s_f + 560;

        // pass A: pair f over nt
        for (int i = tid; i < 496; i += 256) {
            int m = i >> 4, nt = i & 15;
            float4 v;
            if (nt == 0) {
                float2 c = s_f[m * 34 + 15];
                v = make_float4(c.x, c.y, 0.f, 0.f);
            } else {
                float2 fp = s_f[m * 34 + 15 + nt];
                float2 fm = s_f[m * 34 + 15 - nt];
                v = make_float4(fp.x + fm.x, fp.y + fm.y, fp.x - fm.x, fp.y - fm.y);
            }
            s_p4[m * 16 + nt] = v;
        }
        __syncthreads();

        // step 2: g[m,q], 4-way q blocking
        if (tid < 248) {
            int m = tid >> 3, q0 = tid & 7;
            float2 S, E;
            __sincosf((float)q0 * TWOPI_32F, &S.y, &S.x);
            E = S;
            const float4* prow = s_p4 + m * 16;
            float4 c0 = prow[0];
            float a0x = c0.x, a0y = c0.y, a1x = c0.x, a1y = c0.y;
            float a2x = c0.x, a2y = c0.y, a3x = c0.x, a3y = c0.y;
            int nt = 1;
#define S2P(PP)                                                              \
            {                                                                \
                float4 pr = prow[nt];                                        \
                float p1 = E.x * pr.x, p2 = E.y * pr.w;                      \
                float p3 = E.x * pr.y, p4 = E.y * pr.z;                      \
                float tx = p1 - p2, ty = p3 + p4;                            \
                a0x += tx; a0y += ty;                                        \
                if (PP == 0) { a1x += tx; a1y += ty; a2x += tx; a2y += ty;   \
                               a3x += tx; a3y += ty; }                       \
                if (PP == 2) { a1x -= tx; a1y -= ty; a2x += tx; a2y += ty;   \
                               a3x -= tx; a3y -= ty; }                       \
                if (PP == 1 || PP == 3) {                                    \
                    float r1 = E.y * pr.x, r2 = E.x * pr.w;                  \
                    float r3 = E.y * pr.y, r4 = E.x * pr.z;                  \
                    float ux = r1 + r2, uy = r3 - r4;                        \
                    if (PP == 1) { a1x -= ux; a1y -= uy; a2x -= tx;          \
                                   a2y -= ty; a3x += ux; a3y += uy; }        \
                    if (PP == 3) { a1x += ux; a1y += uy; a2x -= tx;          \
                                   a2y -= ty; a3x -= ux; a3y -= uy; }        \
                }                                                            \
                float ex = E.x * S.x - E.y * S.y;                            \
                E.y = E.x * S.y + E.y * S.x;                                 \
                E.x = ex;                                                    \
                ++nt;                                                        \
            }
#pragma unroll
            for (int g4 = 0; g4 < 3; ++g4) {
                S2P(1) S2P(2) S2P(3) S2P(0)
            }
            S2P(1) S2P(2) S2P(3)
#undef S2P
            s_g[m * 32 + q0]      = make_float2(a0x, a0y);
            s_g[m * 32 + q0 + 8]  = make_float2(a1x, a1y);
            s_g[m * 32 + q0 + 16] = make_float2(a2x, a2y);
            s_g[m * 32 + q0 + 24] = make_float2(a3x, a3y);
        }
        __syncthreads();

        // pass B: pair g over mt
        for (int i = tid; i < 480; i += 256) {
            int mt = 1 + (i >> 5), q = i & 31;
            float2 gp = s_g[(15 + mt) * 32 + q];
            float2 gm = s_g[(15 - mt) * 32 + q];
            sp3[(mt - 1) * 32 + q] = make_float2(gp.x + gm.x, gp.y - gm.y);
        }
        __syncthreads();

        // step 3 + in-warp pass C
        {
            int q = tid & 31, p0 = tid >> 5;
            float2 S, E;
            __sincosf((float)p0 * TWOPI_32F, &S.y, &S.x);
            E = S;
            float c = s_g[15 * 32 + q].x;
            float a0 = c, a1 = c, a2 = c, a3 = c;
            const float2* pcol = sp3 + q;
            int mt = 1;
#define S3P(PP)                                                              \
            {                                                                \
                float2 v = pcol[(mt - 1) * 32];                              \
                float u1 = E.x * v.x, u2 = E.y * v.y;                        \
                float tx = u1 - u2;                                          \
                a0 += tx;                                                    \
                if (PP == 0) { a1 += tx; a2 += tx; a3 += tx; }               \
                if (PP == 2) { a1 -= tx; a2 += tx; a3 -= tx; }               \
                if (PP == 1 || PP == 3) {                                    \
                    float v1 = E.y * v.x, v2 = E.x * v.y;                    \
                    float ux = v1 + v2;                                      \
                    if (PP == 1) { a1 -= ux; a2 -= tx; a3 += ux; }           \
                    if (PP == 3) { a1 += ux; a2 -= tx; a3 -= ux; }           \
                }                                                            \
                float ex = E.x * S.x - E.y * S.y;                            \
                E.y = E.x * S.y + E.y * S.x;                                 \
                E.x = ex;                                                    \
                ++mt;                                                        \
            }
#pragma unroll
            for (int g4 = 0; g4 < 3; ++g4) {
                S3P(1) S3P(2) S3P(3) S3P(0)
            }
            S3P(1) S3P(2) S3P(3)
#undef S3P
            a0 = fmaxf(a0, 0.f);
            a1 = fmaxf(a1, 0.f);
            a2 = fmaxf(a2, 0.f);
            a3 = fmaxf(a3, 0.f);
            int src = (32 - q) & 31;
            float b0 = __shfl_sync(0xffffffffu, a0, src);
            float b1 = __shfl_sync(0xffffffffu, a1, src);
            float b2 = __shfl_sync(0xffffffffu, a2, src);
            float b3 = __shfl_sync(0xffffffffu, a3, src);
            __syncthreads();
            if (q >= 1 && q <= 15) {
                int qm1 = q - 1;
                sp4[p0 * 17 + qm1]        = make_float2(a0 + b0, a0 - b0);
                sp4[(p0 + 8) * 17 + qm1]  = make_float2(a1 + b1, a1 - b1);
                sp4[(p0 + 16) * 17 + qm1] = make_float2(a2 + b2, a2 - b2);
                sp4[(p0 + 24) * 17 + qm1] = make_float2(a3 + b3, a3 - b3);
            } else if (q == 0) {
                s_r016[p0]      = a0;
                s_r016[p0 + 8]  = a1;
                s_r016[p0 + 16] = a2;
                s_r016[p0 + 24] = a3;
            } else if (q == 16) {
                s_r016[32 + p0]      = a0;
                s_r016[32 + p0 + 8]  = a1;
                s_r016[32 + p0 + 16] = a2;
                s_r016[32 + p0 + 24] = a3;
            }
        }
        __syncthreads();

        // step 4
        {
            int p = tid >> 3, d = tid & 7;
            float2 W1;
            __sincosf((float)d * TWOPI_32F, &W1.y, &W1.x);
            W1.y = -W1.y;
            float2 W = W1;
            float r0 = s_r016[p];
            float r16 = s_r016[32 + p];
            float axv = r0 + ((d & 1) ? -r16 : r16);
            float ayv = 0.f;
            const float2* sd = sp4 + p * 17;
#pragma unroll
            for (int q = 1; q <= 15; ++q) {
                float2 v = sd[q - 1];
                axv += v.x * W.x;
                ayv += v.y * W.y;
                float wx = W.x * W1.x - W.y * W1.y;
                W.y = W.x * W1.y + W.y * W1.x;
                W.x = wx;
            }
            s_u[p * 8 + d] = make_float2(axv, ayv);
        }
        __syncthreads();

        // step 5 (Hermitian half)
        if (tid < 120) {
            int m2 = tid >> 3, d = tid & 7;
            int n2 = 7 + d;
            int mt = m2 - 7;
            float2 W = make_float2(1.f, 0.f), S5;
            {
                float ss, cc;
                __sincosf((float)mt * TWOPI_32F, &ss, &cc);
                S5 = make_float2(cc, -ss);
            }
            float axv = 0.f, ayv = 0.f;
            const float2* ucol = s_u + d;
#pragma unroll
            for (int p = 0; p < 32; ++p) {
                float2 u = ucol[p * 8];
                axv += u.x * W.x - u.y * W.y;
                ayv += u.x * W.y + u.y * W.x;
                float wx = W.x * S5.x - W.y * S5.y;
                W.y = W.x * S5.y + W.y * S5.x;
                W.x = wx;
            }
            size_t plane = (size_t)(2 * bp + bb) * 1024 + f * 32 + j;
            float2* outp = g_xmn + plane * 225;
            outp[m2 * 15 + n2] = make_float2(axv, ayv);
            if (d > 0)
                outp[(14 - m2) * 15 + (14 - n2)] = make_float2(axv, -ayv);
        }
        __syncthreads();
    }
}

// ------------------------- k_G: xmn -> xh2 -> G (per (b,c)) ----------------
__global__ __launch_bounds__(512) void k_G() {
    __shared__ float2 s_xh2[2 * 8 * 225];
    __shared__ float  s_d2i0[1800];
    int bc = blockIdx.x;
    int tid = threadIdx.x;  // 512

    for (int i = tid; i < 1800; i += 512) s_d2i0[i] = g_D2I0[i];

    if (tid < 450) {
        int jh = tid / 225, mk = tid % 225;
        float2 acc[8];
#pragma unroll
        for (int l = 0; l < 8; ++l) acc[l] = make_float2(0.f, 0.f);
        const float2* xp = g_xmn + (size_t)bc * 7200 + jh * 16 * 225 + mk;
        const float* dp = g_D2F + jh * 16 * 225 + mk;
#pragma unroll 4
        for (int j = 0; j < 16; ++j) {
            float2 xv = xp[j * 225];
#pragma unroll
            for (int l = 0; l < 8; ++l) {
                float d = dp[l * 7200 + j * 225];
                acc[l].x += d * xv.x;
                acc[l].y += d * xv.y;
            }
        }
#pragma unroll
        for (int l = 0; l < 8; ++l)
            s_xh2[jh * 1800 + l * 225 + mk] = acc[l];
    }
    __syncthreads();

    for (int i = tid; i < 1800; i += 512) {
        float2 a = s_xh2[i], b = s_xh2[1800 + i];
        s_xh2[i] = make_float2(a.x + b.x, a.y + b.y);
    }
    __syncthreads();

    float2* gout = g_G + (size_t)bc * 1800;
    for (int idx = tid; idx < 1800; idx += 512) {
        int l = idx / 225, nk = idx % 225;
        int n = nk / 15, k = nk % 15;
        float ax = 0.f, ay = 0.f;
        if (abs(n - 7) <= l) {
            const float* dp = s_d2i0 + l * 225 + n;
            const float2* xp = s_xh2 + l * 225 + k;
            for (int m = 7 - l; m <= 7 + l; ++m) {
                float d = dp[m * 15];
                float2 v = xp[m * 15];
                ax += d * v.x;
                ay += d * v.y;
            }
        }
        gout[idx] = make_float2(ax, ay);
    }
}

// ------------------------- k_dot + fused head (last-block) -----------------
// Block (c, ft) = 256 blocks x 512 threads; warp = batch b; fl-loop inside.
// The last block to finish runs the conv1d+BN+FC head inline.
__global__ __launch_bounds__(512) void k_dot(const float* __restrict__ w2r,
                                             const float* __restrict__ w2i,
                                             const float* __restrict__ w3,
                                             const float* __restrict__ b3,
                                             const float* __restrict__ gam,
                                             const float* __restrict__ bet,
                                             const float* __restrict__ fcw,
                                             const float* __restrict__ fcb,
                                             float* __restrict__ out) {
    __shared__ float s_r3[16 * 570];          // 36.5 KB (head phase)
    __shared__ float s_feat[16 * 64];
    __shared__ float s_mu[10], s_rstd[10];
    __shared__ float s_ps[160], s_ps2[160];
    __shared__ int   s_last;

    int c  = blockIdx.x;      // 32
    int ft = blockIdx.y;      // 8
    int tid = threadIdx.x;    // 512
    int b = tid >> 5;
    int lane = tid & 31;

    const float4* X4 = (const float4*)(g_G + ((size_t)b * 32 + c) * 1800);
#pragma unroll 2
    for (int fl = 0; fl < 8; ++fl) {
        int f = ft * 8 + fl;
        const float4* Wr4 = (const float4*)(w2r + ((size_t)c * 64 + f) * 1800);
        const float4* Wi4 = (const float4*)(w2i + ((size_t)c * 64 + f) * 1800);
        float acc = 0.f;
        for (int i = lane; i < 450; i += 32) {
            float4 g0 = X4[2 * i], g1 = X4[2 * i + 1];
            float4 wr = Wr4[i], wi = Wi4[i];
            acc += g0.x * wr.x + g0.y * wi.x + g0.z * wr.y + g0.w * wi.y
                 + g1.x * wr.z + g1.y * wi.z + g1.z * wr.w + g1.w * wi.w;
        }
#pragma unroll
        for (int o = 16; o > 0; o >>= 1)
            acc += __shfl_xor_sync(0xffffffffu, acc, o);
        if (lane == 0)
            g_partial[(c * 8 + ft) * 128 + b * 8 + fl] = acc;
    }

    // release: make this block's partials visible, then count in
    __threadfence();
    __syncthreads();
    if (tid == 0) {
        unsigned int old = atomicAdd(&g_done, 1u);
        s_last = (old == 255u) ? 1 : 0;
        if (s_last) g_done = 0;     // reset for next graph replay
    }
    __syncthreads();
    if (!s_last) return;
    __threadfence();                // acquire side

    // ---------------- head (this block only, 512 threads) ----------------
    for (int idx = tid; idx < 1024; idx += 512) {
        int bb = idx >> 6;
        int f = idx & 63;
        int ftt = f >> 3, fl = f & 7;
        float s = 0.f;
#pragma unroll
        for (int cc = 0; cc < 32; ++cc)
            s += g_partial[(cc * 8 + ftt) * 128 + (bb << 3) + fl];
        s_feat[bb * 64 + f] = fmaxf(s, 0.f);
    }
    __syncthreads();

    for (int idx = tid; idx < 9120; idx += 512) {
        int bb = idx / 570;
        int r = idx % 570;
        int o = r / 57, t = r % 57;
        float s = b3[o];
#pragma unroll
        for (int k = 0; k < 8; ++k)
            s += w3[o * 8 + k] * s_feat[bb * 64 + t + k];
        s_r3[idx] = fmaxf(s, 0.f);
    }
    __syncthreads();

    if (tid < 160) {
        int o = tid >> 4, i = tid & 15;
        float s = 0.f, s2 = 0.f;
        for (int idx2 = i; idx2 < 912; idx2 += 16) {
            int bb = idx2 / 57, t = idx2 % 57;
            float v = s_r3[bb * 570 + o * 57 + t];
            s += v;
            s2 += v * v;
        }
        s_ps[tid] = s;
        s_ps2[tid] = s2;
    }
    __syncthreads();

    if (tid < 10) {
        float s = 0.f, s2 = 0.f;
#pragma unroll
        for (int i = 0; i < 16; ++i) {
            s += s_ps[tid * 16 + i];
            s2 += s_ps2[tid * 16 + i];
        }
        float mu = s / 912.f;
        float var = s2 / 912.f - mu * mu;
        s_mu[tid] = mu;
        s_rstd[tid] = rsqrtf(var + 1e-5f);
    }
    __syncthreads();

    for (int idx = tid; idx < 9120; idx += 512) {
        int o = (idx % 570) / 57;
        s_r3[idx] = gam[o] * (s_r3[idx] - s_mu[o]) * s_rstd[o] + bet[o];
    }
    __syncthreads();

    if (tid < 160) {
        int bb = tid / 10, i = tid % 10;
        float s = fcb[i];
        const float* wr = fcw + i * 570;
        const float* xr = s_r3 + bb * 570;
        for (int z = 0; z < 570; ++z) s += xr[z] * wr[z];
        out[bb * 10 + i] = s;
    }
}

// ---------------------------------------------------------------------------
extern "C" void kernel_launch(void* const* d_in, const int* in_sizes, int n_in,
                              void* d_out, int out_size) {
    const float* x   = (const float*)d_in[0];
    const float* w1r = (const float*)d_in[1];
    const float* w1i = (const float*)d_in[2];
    const float* w2r = (const float*)d_in[3];
    const float* w2i = (const float*)d_in[4];
    const float* c3w = (const float*)d_in[5];
    const float* c3b = (const float*)d_in[6];
    const float* bng = (const float*)d_in[7];
    const float* bnb = (const float*)d_in[8];
    const float* fcw = (const float*)d_in[9];
    const float* fcb = (const float*)d_in[10];
    float* out = (float*)d_out;

    t_tables<<<(599048 + 127) / 128, 128>>>();
    k_xh<<<16 * 31, 64>>>(x);
    k_main<<<8 * 32 * 32, 256>>>(w1r, w1i);
    k_G<<<512, 512>>>();
    k_dot<<<dim3(32, 8), 512>>>(w2r, w2i, c3w, c3b, bng, bnb, fcw, fcb, out);
}

// round 14
// speedup vs baseline: 1.0491x; 1.0491x over previous
#include <cuda_runtime.h>
#include <math.h>

// ---------------------------------------------------------------------------
// S2ConvNet forward pass, sm_103a.
// Shapes: B=16, F1=32, F2=64, B0=32, B1=16, B2=8, M1=31, M2=15.
// ---------------------------------------------------------------------------

#define PI_D 3.141592653589793238462643383279502884
#define TWOPI_32F 0.19634954084936207f   // 2*pi/32

// ------------------------- static device scratch ---------------------------
__device__ float  g_D1F[16 * 64 * 31];                       // [l][j][m]
__device__ __align__(16) float g_D1I[16 * 32 * 31 * 32];     // [l][j][m][n] n padded
__device__ float  g_D2F[8 * 32 * 15 * 15];                   // [l][j][m][k]
__device__ float  g_D2I0[8 * 15 * 15];                       // [l][m][n]
__device__ float2 g_xh[16 * 16 * 31];                        // [b][l][m]
__device__ __align__(16) float2 g_xmn[16 * 32 * 32 * 225];   // [b][c][j][m][k]
__device__ __align__(16) float2 g_G[16 * 32 * 1800];         // [b][c][l][n][k]
__device__ float  g_partial[32 * 8 * 128];

// beta-grid precompute (incl. tan^2(beta/2))
__device__ double g_cb0[64], g_sb0[64], g_w0[64], g_ts0[64];
__device__ double g_cb1[32], g_sb1[32], g_w1[32], g_ts1[32];
__device__ double g_cb2[16], g_sb2[16], g_ts2[16];

__device__ static const double c_F[32] = {
    1.0, 1.0, 2.0, 6.0, 24.0, 120.0, 720.0, 5040.0, 40320.0, 362880.0,
    3628800.0, 39916800.0, 479001600.0, 6227020800.0, 87178291200.0,
    1307674368000.0, 20922789888000.0, 355687428096000.0, 6402373705728000.0,
    121645100408832000.0, 2432902008176640000.0, 51090942171709440000.0,
    1124000727777607680000.0, 25852016738884976640000.0,
    620448401733239439360000.0, 15511210043330985984000000.0,
    403291461126605635584000000.0, 10888869450418352160768000000.0,
    304888344611713860501504000000.0, 8841761993739701954543616000000.0,
    265252859812191058636308480000000.0, 8222838654177922817725562880000000.0
};

__device__ static const double c_R[32] = {
    0.0, 1.0, 1.0/2.0, 1.0/3.0, 1.0/4.0, 1.0/5.0, 1.0/6.0, 1.0/7.0,
    1.0/8.0, 1.0/9.0, 1.0/10.0, 1.0/11.0, 1.0/12.0, 1.0/13.0, 1.0/14.0,
    1.0/15.0, 1.0/16.0, 1.0/17.0, 1.0/18.0, 1.0/19.0, 1.0/20.0, 1.0/21.0,
    1.0/22.0, 1.0/23.0, 1.0/24.0, 1.0/25.0, 1.0/26.0, 1.0/27.0, 1.0/28.0,
    1.0/29.0, 1.0/30.0, 1.0/31.0
};

__device__ __forceinline__ double ipow_d(double x, int e) {
    double r = 1.0;
    while (e) { if (e & 1) r *= x; x *= x; e >>= 1; }
    return r;
}

__device__ double wig_fast(int l, int m, int n, double cb, double sb, double ts) {
    int kmin = max(0, m - n);
    int kmax = min(l + m, l - n);
    if (kmax < kmin) return 0.0;
    double t = sqrt(c_F[l + m] * c_F[l - m] * c_F[l + n] * c_F[l - n])
             / (c_F[kmin] * c_F[l + m - kmin] * c_F[l - n - kmin] * c_F[n - m + kmin]);
    t *= ipow_d(cb, 2 * l + m - n - 2 * kmin) * ipow_d(sb, n - m + 2 * kmin);
    if (kmin & 1) t = -t;
    double s = t;
    for (int k = kmin; k < kmax; ++k) {
        t *= -((double)((l + m - k) * (l - n - k)) *
               c_R[k + 1] * c_R[n - m + k + 1]) * ts;
        s += t;
    }
    return s;
}

// ------------------------- setup kernel ------------------------------------
__global__ void t_setup() {
    int t = threadIdx.x;   // 64
    if (t < 64) {
        double beta = PI_D * (2.0 * t + 1.0) / 128.0;
        double sb, cb;
        sincos(beta * 0.5, &sb, &cb);
        g_cb0[t] = cb; g_sb0[t] = sb;
        g_ts0[t] = (sb * sb) / (cb * cb);
        double sinb = 2.0 * sb * cb;
        double c2 = 1.0 - 2.0 * sinb * sinb;
        double prev = -sinb, cur = sinb, s = 0.0;
#pragma unroll
        for (int k = 0; k < 32; ++k) {
            s += cur * (1.0 / (2.0 * k + 1.0));
            double nx = 2.0 * c2 * cur - prev;
            prev = cur; cur = nx;
        }
        g_w0[t] = (2.0 / 32.0) * sinb * s;
    }
    if (t < 32) {
        double beta = PI_D * (2.0 * t + 1.0) / 64.0;
        double sb, cb;
        sincos(beta * 0.5, &sb, &cb);
        g_cb1[t] = cb; g_sb1[t] = sb;
        g_ts1[t] = (sb * sb) / (cb * cb);
        double sinb = 2.0 * sb * cb;
        double c2 = 1.0 - 2.0 * sinb * sinb;
        double prev = -sinb, cur = sinb, s = 0.0;
#pragma unroll
        for (int k = 0; k < 16; ++k) {
            s += cur * (1.0 / (2.0 * k + 1.0));
            double nx = 2.0 * c2 * cur - prev;
            prev = cur; cur = nx;
        }
        g_w1[t] = (2.0 / 16.0) * sinb * s;
    }
    if (t < 16) {
        double beta = PI_D * (2.0 * t + 1.0) / 32.0;
        double sb, cb;
        sincos(beta * 0.5, &sb, &cb);
        g_cb2[t] = cb; g_sb2[t] = sb;
        g_ts2[t] = (sb * sb) / (cb * cb);
    }
}

// ------------------------- merged table kernel -----------------------------
__global__ void t_tables() {
    int idx = blockIdx.x * blockDim.x + threadIdx.x;
    if (idx < 31744) {
        int l = idx / (64 * 31);
        int j = (idx / 31) % 64;
        int m = idx % 31;
        int mt = m - 15;
        float* base = g_D1F + (size_t)l * 64 * 31 + (size_t)j * 31;
        if (abs(mt) > l) { base[m] = 0.f; return; }
        if (mt < 0) return;
        float v = (float)(g_w0[j] * wig_fast(l, mt, 0, g_cb0[j], g_sb0[j], g_ts0[j]));
        base[m] = v;
        base[30 - m] = (mt & 1) ? -v : v;
        return;
    }
    idx -= 31744;
    if (idx < 507904) {
        int l = idx / 31744;
        int r = idx % 31744;
        int j = r / 992;
        int m = (r / 32) % 31;
        int n = r % 32;
        float* base = g_D1I + (size_t)l * 31744 + (size_t)j * 992;
        if (n == 31) { base[m * 32 + 31] = 0.f; return; }
        int mt = m - 15, nt = n - 15;
        if (abs(mt) > l || abs(nt) > l) { base[m * 32 + n] = 0.f; return; }
        if (nt < abs(mt)) return;
        float vf = (float)((2.0 * l + 1.0) *
                           wig_fast(l, mt, nt, g_cb1[j], g_sb1[j], g_ts1[j]));
        float sv = ((m - n) & 1) ? -vf : vf;
        base[m * 32 + n] = vf;
        base[n * 32 + m] = sv;
        base[(30 - m) * 32 + (30 - n)] = sv;
        base[(30 - n) * 32 + (30 - m)] = vf;
        return;
    }
    idx -= 507904;
    if (idx < 57600) {
        int l = idx / (32 * 225);
        int j = (idx / 225) % 32;
        int m = (idx / 15) % 15;
        int n = idx % 15;
        int mt = m - 7, nt = n - 7;
        float v = 0.f;
        if (abs(mt) <= l && abs(nt) <= l)
            v = (float)(g_w1[j] * wig_fast(l, mt, nt, g_cb1[j], g_sb1[j], g_ts1[j]));
        g_D2F[idx] = v;
        return;
    }
    idx -= 57600;
    if (idx < 1800) {
        int l = idx / 225;
        int m = (idx / 15) % 15;
        int n = idx % 15;
        int mt = m - 7, nt = n - 7;
        float v = 0.f;
        if (abs(mt) <= l && abs(nt) <= l)
            v = (float)((2.0 * l + 1.0) * wig_fast(l, mt, nt, g_cb2[0], g_sb2[0], g_ts2[0]));
        g_D2I0[idx] = v;
    }
}

// ------------------------- stage A: x -> xh --------------------------------
__global__ void k_xh(const float* __restrict__ x) {
    __shared__ float2 s_tw[64];
    __shared__ float2 s_xm[64];
    int b = blockIdx.x / 31;
    int m = blockIdx.x % 31;
    int mt = m - 15;
    int j = threadIdx.x;   // 64

    float sj, cj;
    __sincosf((float)j * (6.2831853071795864769f / 64.f), &sj, &cj);
    s_tw[j] = make_float2(cj, sj);
    __syncthreads();

    const float* xr = x + (size_t)(b * 64 + j) * 64;
    float accx = 0.f, accy = 0.f;
#pragma unroll 8
    for (int t = 0; t < 64; ++t) {
        unsigned r = ((unsigned)(mt * t)) & 63u;
        float2 e = s_tw[r];
        float v = xr[t];
        accx += v * e.x;
        accy -= v * e.y;
    }
    s_xm[j] = make_float2(accx, accy);
    __syncthreads();

    if (j < 16) {
        int l = j;
        float ax = 0.f, ay = 0.f;
        const float* dp = g_D1F + (size_t)l * 64 * 31 + m;
#pragma unroll 8
        for (int jj = 0; jj < 64; ++jj) {
            float d = dp[jj * 31];
            float2 v = s_xm[jj];
            ax += d * v.x;
            ay += d * v.y;
        }
        g_xh[(b * 16 + l) * 31 + m] = make_float2(ax, ay);
    }
}

// ------------------------- stage B+C fused plane kernel (b-paired) ---------
__global__ __launch_bounds__(256, 3) void k_main(const float* __restrict__ w1r,
                                                 const float* __restrict__ w1i) {
    __shared__ float2 s_xh2[2 * 496];                  // 7.9 KB
    __shared__ __align__(16) float2 s_w1[16 * 32];     // 4 KB
    __shared__ __align__(16) float2 s_f2[2 * 1056];    // 16.9 KB
    __shared__ float2 s_g[31 * 32];                    // 7.9 KB
    __shared__ __align__(16) float4 s_p4[31 * 16];     // 7.9 KB
    __shared__ float  s_r016[64];

    float2* sp3 = (float2*)s_p4;

    int bx = blockIdx.x;
    int bp = bx >> 10;
    int f = (bx >> 5) & 31;
    int j = bx & 31;
    int tid = threadIdx.x;

    for (int i = tid; i < 992; i += 256)
        s_xh2[i] = g_xh[(2 * bp) * 496 + i];
    for (int i = tid; i < 496; i += 256) {
        int l = i / 31, n = i % 31;
        s_w1[l * 32 + n] = make_float2(w1r[f * 496 + i], w1i[f * 496 + i]);
    }
    if (tid < 16) s_w1[tid * 32 + 31] = make_float2(0.f, 0.f);
    __syncthreads();

    // step 1 (both planes)
    if (tid < 248) {
        int m = tid >> 3, ng = tid & 7, n0 = ng * 4;
        int am = abs(m - 15);
        int nhi = n0 + 3;
        int anmin = (nhi < 15) ? (15 - nhi) : ((n0 > 15) ? (n0 - 15) : 0);
        int l0 = max(am, anmin);
        float ax[2][4] = {{0.f, 0.f, 0.f, 0.f}, {0.f, 0.f, 0.f, 0.f}};
        float ay[2][4] = {{0.f, 0.f, 0.f, 0.f}, {0.f, 0.f, 0.f, 0.f}};
        const float4* dp4 = (const float4*)(g_D1I + (size_t)j * 992 + m * 32 + n0);
        for (int l = l0; l < 16; ++l) {
            float4 d = dp4[l * 7936];
            float2 aA = s_xh2[l * 31 + m];
            float2 aB = s_xh2[496 + l * 31 + m];
            float4 wA = *(const float4*)(s_w1 + l * 32 + n0);
            float4 wB = *(const float4*)(s_w1 + l * 32 + n0 + 2);
            float wx[4] = {wA.x, wA.z, wB.x, wB.z};
            float wy[4] = {wA.y, wA.w, wB.y, wB.w};
            float dv[4] = {d.x, d.y, d.z, d.w};
#pragma unroll
            for (int k = 0; k < 4; ++k) {
                float tr = aA.x * wx[k] + aA.y * wy[k];
                float ti = aA.y * wx[k] - aA.x * wy[k];
                ax[0][k] += dv[k] * tr; ay[0][k] += dv[k] * ti;
                tr = aB.x * wx[k] + aB.y * wy[k];
                ti = aB.y * wx[k] - aB.x * wy[k];
                ax[1][k] += dv[k] * tr; ay[1][k] += dv[k] * ti;
            }
        }
#pragma unroll
        for (int bb = 0; bb < 2; ++bb) {
            float2* sf = s_f2 + bb * 1056;
            *(float4*)(sf + m * 34 + n0)     = make_float4(ax[bb][0], ay[bb][0], ax[bb][1], ay[bb][1]);
            *(float4*)(sf + m * 34 + n0 + 2) = make_float4(ax[bb][2], ay[bb][2], ax[bb][3], ay[bb][3]);
        }
    }
    __syncthreads();

    for (int bb = 0; bb < 2; ++bb) {
        float2* s_f = s_f2 + bb * 1056;
        float2* sp4 = s_f;
        float2* s_u = s_f + 560;

        // pass A: pair f over nt
        for (int i = tid; i < 496; i += 256) {
            int m = i >> 4, nt = i & 15;
            float4 v;
            if (nt == 0) {
                float2 c = s_f[m * 34 + 15];
                v = make_float4(c.x, c.y, 0.f, 0.f);
            } else {
                float2 fp = s_f[m * 34 + 15 + nt];
                float2 fm = s_f[m * 34 + 15 - nt];
                v = make_float4(fp.x + fm.x, fp.y + fm.y, fp.x - fm.x, fp.y - fm.y);
            }
            s_p4[m * 16 + nt] = v;
        }
        __syncthreads();

        // step 2: g[m,q], 4-way q blocking
        if (tid < 248) {
            int m = tid >> 3, q0 = tid & 7;
            float2 S, E;
            __sincosf((float)q0 * TWOPI_32F, &S.y, &S.x);
            E = S;
            const float4* prow = s_p4 + m * 16;
            float4 c0 = prow[0];
            float a0x = c0.x, a0y = c0.y, a1x = c0.x, a1y = c0.y;
            float a2x = c0.x, a2y = c0.y, a3x = c0.x, a3y = c0.y;
            int nt = 1;
#define S2P(PP)                                                              \
            {                                                                \
                float4 pr = prow[nt];                                        \
                float p1 = E.x * pr.x, p2 = E.y * pr.w;                      \
                float p3 = E.x * pr.y, p4 = E.y * pr.z;                      \
                float tx = p1 - p2, ty = p3 + p4;                            \
                a0x += tx; a0y += ty;                                        \
                if (PP == 0) { a1x += tx; a1y += ty; a2x += tx; a2y += ty;   \
                               a3x += tx; a3y += ty; }                       \
                if (PP == 2) { a1x -= tx; a1y -= ty; a2x += tx; a2y += ty;   \
                               a3x -= tx; a3y -= ty; }                       \
                if (PP == 1 || PP == 3) {                                    \
                    float r1 = E.y * pr.x, r2 = E.x * pr.w;                  \
                    float r3 = E.y * pr.y, r4 = E.x * pr.z;                  \
                    float ux = r1 + r2, uy = r3 - r4;                        \
                    if (PP == 1) { a1x -= ux; a1y -= uy; a2x -= tx;          \
                                   a2y -= ty; a3x += ux; a3y += uy; }        \
                    if (PP == 3) { a1x += ux; a1y += uy; a2x -= tx;          \
                                   a2y -= ty; a3x -= ux; a3y -= uy; }        \
                }                                                            \
                float ex = E.x * S.x - E.y * S.y;                            \
                E.y = E.x * S.y + E.y * S.x;                                 \
                E.x = ex;                                                    \
                ++nt;                                                        \
            }
#pragma unroll
            for (int g4 = 0; g4 < 3; ++g4) {
                S2P(1) S2P(2) S2P(3) S2P(0)
            }
            S2P(1) S2P(2) S2P(3)
#undef S2P
            s_g[m * 32 + q0]      = make_float2(a0x, a0y);
            s_g[m * 32 + q0 + 8]  = make_float2(a1x, a1y);
            s_g[m * 32 + q0 + 16] = make_float2(a2x, a2y);
            s_g[m * 32 + q0 + 24] = make_float2(a3x, a3y);
        }
        __syncthreads();

        // pass B: pair g over mt
        for (int i = tid; i < 480; i += 256) {
            int mt = 1 + (i >> 5), q = i & 31;
            float2 gp = s_g[(15 + mt) * 32 + q];
            float2 gm = s_g[(15 - mt) * 32 + q];
            sp3[(mt - 1) * 32 + q] = make_float2(gp.x + gm.x, gp.y - gm.y);
        }
        __syncthreads();

        // step 3 + in-warp pass C
        {
            int q = tid & 31, p0 = tid >> 5;
            float2 S, E;
            __sincosf((float)p0 * TWOPI_32F, &S.y, &S.x);
            E = S;
            float c = s_g[15 * 32 + q].x;
            float a0 = c, a1 = c, a2 = c, a3 = c;
            const float2* pcol = sp3 + q;
            int mt = 1;
#define S3P(PP)                                                              \
            {                                                                \
                float2 v = pcol[(mt - 1) * 32];                              \
                float u1 = E.x * v.x, u2 = E.y * v.y;                        \
                float tx = u1 - u2;                                          \
                a0 += tx;                                                    \
                if (PP == 0) { a1 += tx; a2 += tx; a3 += tx; }               \
                if (PP == 2) { a1 -= tx; a2 += tx; a3 -= tx; }               \
                if (PP == 1 || PP == 3) {                                    \
                    float v1 = E.y * v.x, v2 = E.x * v.y;                    \
                    float ux = v1 + v2;                                      \
                    if (PP == 1) { a1 -= ux; a2 -= tx; a3 += ux; }           \
                    if (PP == 3) { a1 += ux; a2 -= tx; a3 -= ux; }           \
                }                                                            \
                float ex = E.x * S.x - E.y * S.y;                            \
                E.y = E.x * S.y + E.y * S.x;                                 \
                E.x = ex;                                                    \
                ++mt;                                                        \
            }
#pragma unroll
            for (int g4 = 0; g4 < 3; ++g4) {
                S3P(1) S3P(2) S3P(3) S3P(0)
            }
            S3P(1) S3P(2) S3P(3)
#undef S3P
            a0 = fmaxf(a0, 0.f);
            a1 = fmaxf(a1, 0.f);
            a2 = fmaxf(a2, 0.f);
            a3 = fmaxf(a3, 0.f);
            int src = (32 - q) & 31;
            float b0 = __shfl_sync(0xffffffffu, a0, src);
            float b1 = __shfl_sync(0xffffffffu, a1, src);
            float b2 = __shfl_sync(0xffffffffu, a2, src);
            float b3 = __shfl_sync(0xffffffffu, a3, src);
            __syncthreads();
            if (q >= 1 && q <= 15) {
                int qm1 = q - 1;
                sp4[p0 * 17 + qm1]        = make_float2(a0 + b0, a0 - b0);
                sp4[(p0 + 8) * 17 + qm1]  = make_float2(a1 + b1, a1 - b1);
                sp4[(p0 + 16) * 17 + qm1] = make_float2(a2 + b2, a2 - b2);
                sp4[(p0 + 24) * 17 + qm1] = make_float2(a3 + b3, a3 - b3);
            } else if (q == 0) {
                s_r016[p0]      = a0;
                s_r016[p0 + 8]  = a1;
                s_r016[p0 + 16] = a2;
                s_r016[p0 + 24] = a3;
            } else if (q == 16) {
                s_r016[32 + p0]      = a0;
                s_r016[32 + p0 + 8]  = a1;
                s_r016[32 + p0 + 16] = a2;
                s_r016[32 + p0 + 24] = a3;
            }
        }
        __syncthreads();

        // step 4
        {
            int p = tid >> 3, d = tid & 7;
            float2 W1;
            __sincosf((float)d * TWOPI_32F, &W1.y, &W1.x);
            W1.y = -W1.y;
            float2 W = W1;
            float r0 = s_r016[p];
            float r16 = s_r016[32 + p];
            float axv = r0 + ((d & 1) ? -r16 : r16);
            float ayv = 0.f;
            const float2* sd = sp4 + p * 17;
#pragma unroll
            for (int q = 1; q <= 15; ++q) {
                float2 v = sd[q - 1];
                axv += v.x * W.x;
                ayv += v.y * W.y;
                float wx = W.x * W1.x - W.y * W1.y;
                W.y = W.x * W1.y + W.y * W1.x;
                W.x = wx;
            }
            s_u[p * 8 + d] = make_float2(axv, ayv);
        }
        __syncthreads();

        // step 5 (Hermitian half)
        if (tid < 120) {
            int m2 = tid >> 3, d = tid & 7;
            int n2 = 7 + d;
            int mt = m2 - 7;
            float2 W = make_float2(1.f, 0.f), S5;
            {
                float ss, cc;
                __sincosf((float)mt * TWOPI_32F, &ss, &cc);
                S5 = make_float2(cc, -ss);
            }
            float axv = 0.f, ayv = 0.f;
            const float2* ucol = s_u + d;
#pragma unroll
            for (int p = 0; p < 32; ++p) {
                float2 u = ucol[p * 8];
                axv += u.x * W.x - u.y * W.y;
                ayv += u.x * W.y + u.y * W.x;
                float wx = W.x * S5.x - W.y * S5.y;
                W.y = W.x * S5.y + W.y * S5.x;
                W.x = wx;
            }
            size_t plane = (size_t)(2 * bp + bb) * 1024 + f * 32 + j;
            float2* outp = g_xmn + plane * 225;
            outp[m2 * 15 + n2] = make_float2(axv, ayv);
            if (d > 0)
                outp[(14 - m2) * 15 + (14 - n2)] = make_float2(axv, -ayv);
        }
        __syncthreads();
    }
}

// ------------------------- k_G: xmn -> xh2 -> G (per (b,c)) ----------------
__global__ __launch_bounds__(512) void k_G() {
    __shared__ float2 s_xh2[2 * 8 * 225];
    __shared__ float  s_d2i0[1800];
    int bc = blockIdx.x;
    int tid = threadIdx.x;  // 512

    for (int i = tid; i < 1800; i += 512) s_d2i0[i] = g_D2I0[i];

    if (tid < 450) {
        int jh = tid / 225, mk = tid % 225;
        float2 acc[8];
#pragma unroll
        for (int l = 0; l < 8; ++l) acc[l] = make_float2(0.f, 0.f);
        const float2* xp = g_xmn + (size_t)bc * 7200 + jh * 16 * 225 + mk;
        const float* dp = g_D2F + jh * 16 * 225 + mk;
#pragma unroll 4
        for (int j = 0; j < 16; ++j) {
            float2 xv = xp[j * 225];
#pragma unroll
            for (int l = 0; l < 8; ++l) {
                float d = dp[l * 7200 + j * 225];
                acc[l].x += d * xv.x;
                acc[l].y += d * xv.y;
            }
        }
#pragma unroll
        for (int l = 0; l < 8; ++l)
            s_xh2[jh * 1800 + l * 225 + mk] = acc[l];
    }
    __syncthreads();

    for (int i = tid; i < 1800; i += 512) {
        float2 a = s_xh2[i], b = s_xh2[1800 + i];
        s_xh2[i] = make_float2(a.x + b.x, a.y + b.y);
    }
    __syncthreads();

    float2* gout = g_G + (size_t)bc * 1800;
    for (int idx = tid; idx < 1800; idx += 512) {
        int l = idx / 225, nk = idx % 225;
        int n = nk / 15, k = nk % 15;
        float ax = 0.f, ay = 0.f;
        if (abs(n - 7) <= l) {
            const float* dp = s_d2i0 + l * 225 + n;
            const float2* xp = s_xh2 + l * 225 + k;
            for (int m = 7 - l; m <= 7 + l; ++m) {
                float d = dp[m * 15];
                float2 v = xp[m * 15];
                ax += d * v.x;
                ay += d * v.y;
            }
        }
        gout[idx] = make_float2(ax, ay);
    }
}

// ------------------------- k_dot: warp-per-b, fl-loop (G L2 reuse) ---------
__global__ __launch_bounds__(512) void k_dot(const float* __restrict__ w2r,
                                             const float* __restrict__ w2i) {
    int c  = blockIdx.x;      // 32
    int ft = blockIdx.y;      // 8
    int tid = threadIdx.x;    // 512
    int b = tid >> 5;         // warp = batch 0..15
    int lane = tid & 31;

    const float4* X4 = (const float4*)(g_G + ((size_t)b * 32 + c) * 1800);
#pragma unroll 2
    for (int fl = 0; fl < 8; ++fl) {
        int f = ft * 8 + fl;
        const float4* Wr4 = (const float4*)(w2r + ((size_t)c * 64 + f) * 1800);
        const float4* Wi4 = (const float4*)(w2i + ((size_t)c * 64 + f) * 1800);
        float acc = 0.f;
        for (int i = lane; i < 450; i += 32) {
            float4 g0 = X4[2 * i], g1 = X4[2 * i + 1];
            float4 wr = Wr4[i], wi = Wi4[i];
            acc += g0.x * wr.x + g0.y * wi.x + g0.z * wr.y + g0.w * wi.y
                 + g1.x * wr.z + g1.y * wi.z + g1.z * wr.w + g1.w * wi.w;
        }
#pragma unroll
        for (int o = 16; o > 0; o >>= 1)
            acc += __shfl_xor_sync(0xffffffffu, acc, o);
        if (lane == 0)
            g_partial[(c * 8 + ft) * 128 + b * 8 + fl] = acc;
    }
}

// ------------------------- head: reduce + conv1d + BN + FC -----------------
__global__ void k_head(const float* __restrict__ w3, const float* __restrict__ b3,
                       const float* __restrict__ gam, const float* __restrict__ bet,
                       const float* __restrict__ fcw, const float* __restrict__ fcb,
                       float* __restrict__ out) {
    __shared__ float s_feat[16 * 64];
    __shared__ float s_r3[16 * 570];
    __shared__ float s_mu[10], s_rstd[10];
    __shared__ float s_ps[160], s_ps2[160];
    int tid = threadIdx.x;    // 256

    for (int idx = tid; idx < 1024; idx += 256) {
        int b = idx >> 6;
        int f = idx & 63;
        int ft = f >> 3, fl = f & 7;
        float s = 0.f;
#pragma unroll
        for (int c = 0; c < 32; ++c)
            s += g_partial[(c * 8 + ft) * 128 + (b << 3) + fl];
        s_feat[b * 64 + f] = fmaxf(s, 0.f);
    }
    __syncthreads();

    for (int idx = tid; idx < 9120; idx += 256) {
        int b = idx / 570;
        int r = idx % 570;
        int o = r / 57, t = r % 57;
        float s = b3[o];
#pragma unroll
        for (int k = 0; k < 8; ++k)
            s += w3[o * 8 + k] * s_feat[b * 64 + t + k];
        s_r3[idx] = fmaxf(s, 0.f);
    }
    __syncthreads();

    if (tid < 160) {
        int o = tid >> 4, i = tid & 15;
        float s = 0.f, s2 = 0.f;
        for (int idx2 = i; idx2 < 912; idx2 += 16) {
            int b = idx2 / 57, t = idx2 % 57;
            float v = s_r3[b * 570 + o * 57 + t];
            s += v;
            s2 += v * v;
        }
        s_ps[tid] = s;
        s_ps2[tid] = s2;
    }
    __syncthreads();

    if (tid < 10) {
        float s = 0.f, s2 = 0.f;
#pragma unroll
        for (int i = 0; i < 16; ++i) {
            s += s_ps[tid * 16 + i];
            s2 += s_ps2[tid * 16 + i];
        }
        float mu = s / 912.f;
        float var = s2 / 912.f - mu * mu;
        s_mu[tid] = mu;
        s_rstd[tid] = rsqrtf(var + 1e-5f);
    }
    __syncthreads();

    for (int idx = tid; idx < 9120; idx += 256) {
        int o = (idx % 570) / 57;
        s_r3[idx] = gam[o] * (s_r3[idx] - s_mu[o]) * s_rstd[o] + bet[o];
    }
    __syncthreads();

    if (tid < 160) {
        int b = tid / 10, i = tid % 10;
        float s = fcb[i];
        const float* wr = fcw + i * 570;
        const float* xr = s_r3 + b * 570;
        for (int z = 0; z < 570; ++z) s += xr[z] * wr[z];
        out[b * 10 + i] = s;
    }
}

// ---------------------------------------------------------------------------
extern "C" void kernel_launch(void* const* d_in, const int* in_sizes, int n_in,
                              void* d_out, int out_size) {
    const float* x   = (const float*)d_in[0];
    const float* w1r = (const float*)d_in[1];
    const float* w1i = (const float*)d_in[2];
    const float* w2r = (const float*)d_in[3];
    const float* w2i = (const float*)d_in[4];
    const float* c3w = (const float*)d_in[5];
    const float* c3b = (const float*)d_in[6];
    const float* bng = (const float*)d_in[7];
    const float* bnb = (const float*)d_in[8];
    const float* fcw = (const float*)d_in[9];
    const float* fcb = (const float*)d_in[10];
    float* out = (float*)d_out;

    t_setup<<<1, 64>>>();
    t_tables<<<(599048 + 127) / 128, 128>>>();

    k_xh<<<16 * 31, 64>>>(x);
    k_main<<<8 * 32 * 32, 256>>>(w1r, w1i);
    k_G<<<512, 512>>>();
    k_dot<<<dim3(32, 8), 512>>>(w2r, w2i);
    k_head<<<1, 256>>>(c3w, c3b, bng, bnb, fcw, fcb, out);
}

// round 15
// speedup vs baseline: 1.1265x; 1.0739x over previous
#include <cuda_runtime.h>
#include <math.h>

// ---------------------------------------------------------------------------
// S2ConvNet forward pass, sm_103a.
// Shapes: B=16, F1=32, F2=64, B0=32, B1=16, B2=8, M1=31, M2=15.
// ---------------------------------------------------------------------------

#define PI_D 3.141592653589793238462643383279502884
#define TWOPI_32F 0.19634954084936207f   // 2*pi/32

// ------------------------- static device scratch ---------------------------
__device__ float  g_D1F[16 * 64 * 31];                       // [l][j][m]
__device__ __align__(16) float g_D1I[16 * 32 * 31 * 32];     // [l][j][m][n] n padded
__device__ float  g_D2F[8 * 32 * 15 * 15];                   // [l][j][m][k]
__device__ float  g_D2I0[8 * 15 * 15];                       // [l][m][n]
__device__ float2 g_xh[16 * 16 * 31];                        // [b][l][m]
__device__ __align__(16) float2 g_xmn[16 * 32 * 32 * 225];   // [b][c][j][m][k]
__device__ __align__(16) float2 g_G[16 * 32 * 1800];         // [b][c][l][n][k]
__device__ float  g_partial[32 * 8 * 128];
__device__ int    g_wedge[1496];          // packed (l<<10)|(m<<5)|n canonical list

// beta-grid precompute (incl. tan^2(beta/2))
__device__ double g_cb0[64], g_sb0[64], g_w0[64], g_ts0[64];
__device__ double g_cb1[32], g_sb1[32], g_w1[32], g_ts1[32];
__device__ double g_cb2[16], g_sb2[16], g_ts2[16];

__device__ static const double c_F[32] = {
    1.0, 1.0, 2.0, 6.0, 24.0, 120.0, 720.0, 5040.0, 40320.0, 362880.0,
    3628800.0, 39916800.0, 479001600.0, 6227020800.0, 87178291200.0,
    1307674368000.0, 20922789888000.0, 355687428096000.0, 6402373705728000.0,
    121645100408832000.0, 2432902008176640000.0, 51090942171709440000.0,
    1124000727777607680000.0, 25852016738884976640000.0,
    620448401733239439360000.0, 15511210043330985984000000.0,
    403291461126605635584000000.0, 10888869450418352160768000000.0,
    304888344611713860501504000000.0, 8841761993739701954543616000000.0,
    265252859812191058636308480000000.0, 8222838654177922817725562880000000.0
};

__device__ static const double c_R[32] = {
    0.0, 1.0, 1.0/2.0, 1.0/3.0, 1.0/4.0, 1.0/5.0, 1.0/6.0, 1.0/7.0,
    1.0/8.0, 1.0/9.0, 1.0/10.0, 1.0/11.0, 1.0/12.0, 1.0/13.0, 1.0/14.0,
    1.0/15.0, 1.0/16.0, 1.0/17.0, 1.0/18.0, 1.0/19.0, 1.0/20.0, 1.0/21.0,
    1.0/22.0, 1.0/23.0, 1.0/24.0, 1.0/25.0, 1.0/26.0, 1.0/27.0, 1.0/28.0,
    1.0/29.0, 1.0/30.0, 1.0/31.0
};

__device__ __forceinline__ double ipow_d(double x, int e) {
    double r = 1.0;
    while (e) { if (e & 1) r *= x; x *= x; e >>= 1; }
    return r;
}

__device__ double wig_fast(int l, int m, int n, double cb, double sb, double ts) {
    int kmin = max(0, m - n);
    int kmax = min(l + m, l - n);
    if (kmax < kmin) return 0.0;
    double t = sqrt(c_F[l + m] * c_F[l - m] * c_F[l + n] * c_F[l - n])
             / (c_F[kmin] * c_F[l + m - kmin] * c_F[l - n - kmin] * c_F[n - m + kmin]);
    t *= ipow_d(cb, 2 * l + m - n - 2 * kmin) * ipow_d(sb, n - m + 2 * kmin);
    if (kmin & 1) t = -t;
    double s = t;
    for (int k = kmin; k < kmax; ++k) {
        t *= -((double)((l + m - k) * (l - n - k)) *
               c_R[k + 1] * c_R[n - m + k + 1]) * ts;
        s += t;
    }
    return s;
}

// ------------------------- setup kernel ------------------------------------
__global__ void t_setup() {
    int t = threadIdx.x;   // 64
    if (t < 64) {
        double beta = PI_D * (2.0 * t + 1.0) / 128.0;
        double sb, cb;
        sincos(beta * 0.5, &sb, &cb);
        g_cb0[t] = cb; g_sb0[t] = sb;
        g_ts0[t] = (sb * sb) / (cb * cb);
        double sinb = 2.0 * sb * cb;
        double c2 = 1.0 - 2.0 * sinb * sinb;
        double prev = -sinb, cur = sinb, s = 0.0;
#pragma unroll
        for (int k = 0; k < 32; ++k) {
            s += cur * (1.0 / (2.0 * k + 1.0));
            double nx = 2.0 * c2 * cur - prev;
            prev = cur; cur = nx;
        }
        g_w0[t] = (2.0 / 32.0) * sinb * s;
    }
    if (t < 32) {
        double beta = PI_D * (2.0 * t + 1.0) / 64.0;
        double sb, cb;
        sincos(beta * 0.5, &sb, &cb);
        g_cb1[t] = cb; g_sb1[t] = sb;
        g_ts1[t] = (sb * sb) / (cb * cb);
        double sinb = 2.0 * sb * cb;
        double c2 = 1.0 - 2.0 * sinb * sinb;
        double prev = -sinb, cur = sinb, s = 0.0;
#pragma unroll
        for (int k = 0; k < 16; ++k) {
            s += cur * (1.0 / (2.0 * k + 1.0));
            double nx = 2.0 * c2 * cur - prev;
            prev = cur; cur = nx;
        }
        g_w1[t] = (2.0 / 16.0) * sinb * s;
    }
    if (t < 16) {
        double beta = PI_D * (2.0 * t + 1.0) / 32.0;
        double sb, cb;
        sincos(beta * 0.5, &sb, &cb);
        g_cb2[t] = cb; g_sb2[t] = sb;
        g_ts2[t] = (sb * sb) / (cb * cb);
        // build canonical wedge list for l = t: entries (mt, nt >= |mt|)
        int off = t * (t + 1) * (2 * t + 1) / 6;   // sum of (l'+1)^2, l' < t
        for (int mt = -t; mt <= t; ++mt) {
            int amt = mt < 0 ? -mt : mt;
            for (int nt = amt; nt <= t; ++nt)
                g_wedge[off++] = (t << 10) | ((mt + 15) << 5) | (nt + 15);
        }
    }
}

// ------------------------- merged table kernel -----------------------------
// Sections: D1F [0,31744) | D1I zero-fill [.., +507904) | D1I canonical
// compact [.., +47872) | D2F [.., +57600) | D2I0 [.., +1800)
__global__ void t_tables() {
    int idx = blockIdx.x * blockDim.x + threadIdx.x;
    if (idx < 31744) {
        int l = idx / (64 * 31);
        int j = (idx / 31) % 64;
        int m = idx % 31;
        int mt = m - 15;
        float* base = g_D1F + (size_t)l * 64 * 31 + (size_t)j * 31;
        if (abs(mt) > l) { base[m] = 0.f; return; }
        if (mt < 0) return;
        float v = (float)(g_w0[j] * wig_fast(l, mt, 0, g_cb0[j], g_sb0[j], g_ts0[j]));
        base[m] = v;
        base[30 - m] = (mt & 1) ? -v : v;
        return;
    }
    idx -= 31744;
    if (idx < 507904) {                     // D1I zero-fill (invalid + padding)
        int l = idx / 31744;
        int r = idx % 31744;
        int j = r / 992;
        int m = (r / 32) % 31;
        int n = r % 32;
        int mt = m - 15, nt = n - 15;
        if (n == 31 || abs(mt) > l || abs(nt) > l)
            g_D1I[(size_t)l * 31744 + (size_t)j * 992 + m * 32 + n] = 0.f;
        return;
    }
    idx -= 507904;
    if (idx < 47872) {                      // D1I canonical compact (32 j x 1496)
        int j = idx / 1496;
        int w = g_wedge[idx % 1496];
        int l = w >> 10;
        int m = (w >> 5) & 31;
        int n = w & 31;
        int mt = m - 15, nt = n - 15;
        float* base = g_D1I + (size_t)l * 31744 + (size_t)j * 992;
        float vf = (float)((2.0 * l + 1.0) *
                           wig_fast(l, mt, nt, g_cb1[j], g_sb1[j], g_ts1[j]));
        float sv = ((m - n) & 1) ? -vf : vf;
        base[m * 32 + n] = vf;
        base[n * 32 + m] = sv;
        base[(30 - m) * 32 + (30 - n)] = sv;
        base[(30 - n) * 32 + (30 - m)] = vf;
        return;
    }
    idx -= 47872;
    if (idx < 57600) {
        int l = idx / (32 * 225);
        int j = (idx / 225) % 32;
        int m = (idx / 15) % 15;
        int n = idx % 15;
        int mt = m - 7, nt = n - 7;
        float v = 0.f;
        if (abs(mt) <= l && abs(nt) <= l)
            v = (float)(g_w1[j] * wig_fast(l, mt, nt, g_cb1[j], g_sb1[j], g_ts1[j]));
        g_D2F[idx] = v;
        return;
    }
    idx -= 57600;
    if (idx < 1800) {
        int l = idx / 225;
        int m = (idx / 15) % 15;
        int n = idx % 15;
        int mt = m - 7, nt = n - 7;
        float v = 0.f;
        if (abs(mt) <= l && abs(nt) <= l)
            v = (float)((2.0 * l + 1.0) * wig_fast(l, mt, nt, g_cb2[0], g_sb2[0], g_ts2[0]));
        g_D2I0[idx] = v;
    }
}

// ------------------------- stage A: x -> xh --------------------------------
__global__ void k_xh(const float* __restrict__ x) {
    __shared__ float2 s_tw[64];
    __shared__ float2 s_xm[64];
    int b = blockIdx.x / 31;
    int m = blockIdx.x % 31;
    int mt = m - 15;
    int j = threadIdx.x;   // 64

    float sj, cj;
    __sincosf((float)j * (6.2831853071795864769f / 64.f), &sj, &cj);
    s_tw[j] = make_float2(cj, sj);
    __syncthreads();

    const float* xr = x + (size_t)(b * 64 + j) * 64;
    float accx = 0.f, accy = 0.f;
#pragma unroll 8
    for (int t = 0; t < 64; ++t) {
        unsigned r = ((unsigned)(mt * t)) & 63u;
        float2 e = s_tw[r];
        float v = xr[t];
        accx += v * e.x;
        accy -= v * e.y;
    }
    s_xm[j] = make_float2(accx, accy);
    __syncthreads();

    if (j < 16) {
        int l = j;
        float ax = 0.f, ay = 0.f;
        const float* dp = g_D1F + (size_t)l * 64 * 31 + m;
#pragma unroll 8
        for (int jj = 0; jj < 64; ++jj) {
            float d = dp[jj * 31];
            float2 v = s_xm[jj];
            ax += d * v.x;
            ay += d * v.y;
        }
        g_xh[(b * 16 + l) * 31 + m] = make_float2(ax, ay);
    }
}

// ------------------------- stage B+C fused plane kernel (b-paired) ---------
__global__ __launch_bounds__(256, 3) void k_main(const float* __restrict__ w1r,
                                                 const float* __restrict__ w1i) {
    __shared__ float2 s_xh2[2 * 496];                  // 7.9 KB
    __shared__ __align__(16) float2 s_w1[16 * 32];     // 4 KB
    __shared__ __align__(16) float2 s_f2[2 * 1056];    // 16.9 KB
    __shared__ float2 s_g[31 * 32];                    // 7.9 KB
    __shared__ __align__(16) float4 s_p4[31 * 16];     // 7.9 KB
    __shared__ float  s_r016[64];

    float2* sp3 = (float2*)s_p4;

    int bx = blockIdx.x;
    int bp = bx >> 10;
    int f = (bx >> 5) & 31;
    int j = bx & 31;
    int tid = threadIdx.x;

    for (int i = tid; i < 992; i += 256)
        s_xh2[i] = g_xh[(2 * bp) * 496 + i];
    for (int i = tid; i < 496; i += 256) {
        int l = i / 31, n = i % 31;
        s_w1[l * 32 + n] = make_float2(w1r[f * 496 + i], w1i[f * 496 + i]);
    }
    if (tid < 16) s_w1[tid * 32 + 31] = make_float2(0.f, 0.f);
    __syncthreads();

    // step 1 (both planes)
    if (tid < 248) {
        int m = tid >> 3, ng = tid & 7, n0 = ng * 4;
        int am = abs(m - 15);
        int nhi = n0 + 3;
        int anmin = (nhi < 15) ? (15 - nhi) : ((n0 > 15) ? (n0 - 15) : 0);
        int l0 = max(am, anmin);
        float ax[2][4] = {{0.f, 0.f, 0.f, 0.f}, {0.f, 0.f, 0.f, 0.f}};
        float ay[2][4] = {{0.f, 0.f, 0.f, 0.f}, {0.f, 0.f, 0.f, 0.f}};
        const float4* dp4 = (const float4*)(g_D1I + (size_t)j * 992 + m * 32 + n0);
        for (int l = l0; l < 16; ++l) {
            float4 d = dp4[l * 7936];
            float2 aA = s_xh2[l * 31 + m];
            float2 aB = s_xh2[496 + l * 31 + m];
            float4 wA = *(const float4*)(s_w1 + l * 32 + n0);
            float4 wB = *(const float4*)(s_w1 + l * 32 + n0 + 2);
            float wx[4] = {wA.x, wA.z, wB.x, wB.z};
            float wy[4] = {wA.y, wA.w, wB.y, wB.w};
            float dv[4] = {d.x, d.y, d.z, d.w};
#pragma unroll
            for (int k = 0; k < 4; ++k) {
                float tr = aA.x * wx[k] + aA.y * wy[k];
                float ti = aA.y * wx[k] - aA.x * wy[k];
                ax[0][k] += dv[k] * tr; ay[0][k] += dv[k] * ti;
                tr = aB.x * wx[k] + aB.y * wy[k];
                ti = aB.y * wx[k] - aB.x * wy[k];
                ax[1][k] += dv[k] * tr; ay[1][k] += dv[k] * ti;
            }
        }
#pragma unroll
        for (int bb = 0; bb < 2; ++bb) {
            float2* sf = s_f2 + bb * 1056;
            *(float4*)(sf + m * 34 + n0)     = make_float4(ax[bb][0], ay[bb][0], ax[bb][1], ay[bb][1]);
            *(float4*)(sf + m * 34 + n0 + 2) = make_float4(ax[bb][2], ay[bb][2], ax[bb][3], ay[bb][3]);
        }
    }
    __syncthreads();

    for (int bb = 0; bb < 2; ++bb) {
        float2* s_f = s_f2 + bb * 1056;
        float2* sp4 = s_f;
        float2* s_u = s_f + 560;

        // pass A: pair f over nt
        for (int i = tid; i < 496; i += 256) {
            int m = i >> 4, nt = i & 15;
            float4 v;
            if (nt == 0) {
                float2 c = s_f[m * 34 + 15];
                v = make_float4(c.x, c.y, 0.f, 0.f);
            } else {
                float2 fp = s_f[m * 34 + 15 + nt];
                float2 fm = s_f[m * 34 + 15 - nt];
                v = make_float4(fp.x + fm.x, fp.y + fm.y, fp.x - fm.x, fp.y - fm.y);
            }
            s_p4[m * 16 + nt] = v;
        }
        __syncthreads();

        // step 2: g[m,q], 4-way q blocking
        if (tid < 248) {
            int m = tid >> 3, q0 = tid & 7;
            float2 S, E;
            __sincosf((float)q0 * TWOPI_32F, &S.y, &S.x);
            E = S;
            const float4* prow = s_p4 + m * 16;
            float4 c0 = prow[0];
            float a0x = c0.x, a0y = c0.y, a1x = c0.x, a1y = c0.y;
            float a2x = c0.x, a2y = c0.y, a3x = c0.x, a3y = c0.y;
            int nt = 1;
#define S2P(PP)                                                              \
            {                                                                \
                float4 pr = prow[nt];                                        \
                float p1 = E.x * pr.x, p2 = E.y * pr.w;                      \
                float p3 = E.x * pr.y, p4 = E.y * pr.z;                      \
                float tx = p1 - p2, ty = p3 + p4;                            \
                a0x += tx; a0y += ty;                                        \
                if (PP == 0) { a1x += tx; a1y += ty; a2x += tx; a2y += ty;   \
                               a3x += tx; a3y += ty; }                       \
                if (PP == 2) { a1x -= tx; a1y -= ty; a2x += tx; a2y += ty;   \
                               a3x -= tx; a3y -= ty; }                       \
                if (PP == 1 || PP == 3) {                                    \
                    float r1 = E.y * pr.x, r2 = E.x * pr.w;                  \
                    float r3 = E.y * pr.y, r4 = E.x * pr.z;                  \
                    float ux = r1 + r2, uy = r3 - r4;                        \
                    if (PP == 1) { a1x -= ux; a1y -= uy; a2x -= tx;          \
                                   a2y -= ty; a3x += ux; a3y += uy; }        \
                    if (PP == 3) { a1x += ux; a1y += uy; a2x -= tx;          \
                                   a2y -= ty; a3x -= ux; a3y -= uy; }        \
                }                                                            \
                float ex = E.x * S.x - E.y * S.y;                            \
                E.y = E.x * S.y + E.y * S.x;                                 \
                E.x = ex;                                                    \
                ++nt;                                                        \
            }
#pragma unroll
            for (int g4 = 0; g4 < 3; ++g4) {
                S2P(1) S2P(2) S2P(3) S2P(0)
            }
            S2P(1) S2P(2) S2P(3)
#undef S2P
            s_g[m * 32 + q0]      = make_float2(a0x, a0y);
            s_g[m * 32 + q0 + 8]  = make_float2(a1x, a1y);
            s_g[m * 32 + q0 + 16] = make_float2(a2x, a2y);
            s_g[m * 32 + q0 + 24] = make_float2(a3x, a3y);
        }
        __syncthreads();

        // pass B: pair g over mt
        for (int i = tid; i < 480; i += 256) {
            int mt = 1 + (i >> 5), q = i & 31;
            float2 gp = s_g[(15 + mt) * 32 + q];
            float2 gm = s_g[(15 - mt) * 32 + q];
            sp3[(mt - 1) * 32 + q] = make_float2(gp.x + gm.x, gp.y - gm.y);
        }
        __syncthreads();

        // step 3 + in-warp pass C
        {
            int q = tid & 31, p0 = tid >> 5;
            float2 S, E;
            __sincosf((float)p0 * TWOPI_32F, &S.y, &S.x);
            E = S;
            float c = s_g[15 * 32 + q].x;
            float a0 = c, a1 = c, a2 = c, a3 = c;
            const float2* pcol = sp3 + q;
            int mt = 1;
#define S3P(PP)                                                              \
            {                                                                \
                float2 v = pcol[(mt - 1) * 32];                              \
                float u1 = E.x * v.x, u2 = E.y * v.y;                        \
                float tx = u1 - u2;                                          \
                a0 += tx;                                                    \
                if (PP == 0) { a1 += tx; a2 += tx; a3 += tx; }               \
                if (PP == 2) { a1 -= tx; a2 += tx; a3 -= tx; }               \
                if (PP == 1 || PP == 3) {                                    \
                    float v1 = E.y * v.x, v2 = E.x * v.y;                    \
                    float ux = v1 + v2;                                      \
                    if (PP == 1) { a1 -= ux; a2 -= tx; a3 += ux; }           \
                    if (PP == 3) { a1 += ux; a2 -= tx; a3 -= ux; }           \
                }                                                            \
                float ex = E.x * S.x - E.y * S.y;                            \
                E.y = E.x * S.y + E.y * S.x;                                 \
                E.x = ex;                                                    \
                ++mt;                                                        \
            }
#pragma unroll
            for (int g4 = 0; g4 < 3; ++g4) {
                S3P(1) S3P(2) S3P(3) S3P(0)
            }
            S3P(1) S3P(2) S3P(3)
#undef S3P
            a0 = fmaxf(a0, 0.f);
            a1 = fmaxf(a1, 0.f);
            a2 = fmaxf(a2, 0.f);
            a3 = fmaxf(a3, 0.f);
            int src = (32 - q) & 31;
            float b0 = __shfl_sync(0xffffffffu, a0, src);
            float b1 = __shfl_sync(0xffffffffu, a1, src);
            float b2 = __shfl_sync(0xffffffffu, a2, src);
            float b3 = __shfl_sync(0xffffffffu, a3, src);
            __syncthreads();
            if (q >= 1 && q <= 15) {
                int qm1 = q - 1;
                sp4[p0 * 17 + qm1]        = make_float2(a0 + b0, a0 - b0);
                sp4[(p0 + 8) * 17 + qm1]  = make_float2(a1 + b1, a1 - b1);
                sp4[(p0 + 16) * 17 + qm1] = make_float2(a2 + b2, a2 - b2);
                sp4[(p0 + 24) * 17 + qm1] = make_float2(a3 + b3, a3 - b3);
            } else if (q == 0) {
                s_r016[p0]      = a0;
                s_r016[p0 + 8]  = a1;
                s_r016[p0 + 16] = a2;
                s_r016[p0 + 24] = a3;
            } else if (q == 16) {
                s_r016[32 + p0]      = a0;
                s_r016[32 + p0 + 8]  = a1;
                s_r016[32 + p0 + 16] = a2;
                s_r016[32 + p0 + 24] = a3;
            }
        }
        __syncthreads();

        // step 4
        {
            int p = tid >> 3, d = tid & 7;
            float2 W1;
            __sincosf((float)d * TWOPI_32F, &W1.y, &W1.x);
            W1.y = -W1.y;
            float2 W = W1;
            float r0 = s_r016[p];
            float r16 = s_r016[32 + p];
            float axv = r0 + ((d & 1) ? -r16 : r16);
            float ayv = 0.f;
            const float2* sd = sp4 + p * 17;
#pragma unroll
            for (int q = 1; q <= 15; ++q) {
                float2 v = sd[q - 1];
                axv += v.x * W.x;
                ayv += v.y * W.y;
                float wx = W.x * W1.x - W.y * W1.y;
                W.y = W.x * W1.y + W.y * W1.x;
                W.x = wx;
            }
            s_u[p * 8 + d] = make_float2(axv, ayv);
        }
        __syncthreads();

        // step 5 (Hermitian half)
        if (tid < 120) {
            int m2 = tid >> 3, d = tid & 7;
            int n2 = 7 + d;
            int mt = m2 - 7;
            float2 W = make_float2(1.f, 0.f), S5;
            {
                float ss, cc;
                __sincosf((float)mt * TWOPI_32F, &ss, &cc);
                S5 = make_float2(cc, -ss);
            }
            float axv = 0.f, ayv = 0.f;
            const float2* ucol = s_u + d;
#pragma unroll
            for (int p = 0; p < 32; ++p) {
                float2 u = ucol[p * 8];
                axv += u.x * W.x - u.y * W.y;
                ayv += u.x * W.y + u.y * W.x;
                float wx = W.x * S5.x - W.y * S5.y;
                W.y = W.x * S5.y + W.y * S5.x;
                W.x = wx;
            }
            size_t plane = (size_t)(2 * bp + bb) * 1024 + f * 32 + j;
            float2* outp = g_xmn + plane * 225;
            outp[m2 * 15 + n2] = make_float2(axv, ayv);
            if (d > 0)
                outp[(14 - m2) * 15 + (14 - n2)] = make_float2(axv, -ayv);
        }
        __syncthreads();
    }
}

// ------------------------- k_G: xmn -> xh2 -> G (per (b,c)) ----------------
__global__ __launch_bounds__(512) void k_G() {
    __shared__ float2 s_xh2[2 * 8 * 225];
    __shared__ float  s_d2i0[1800];
    int bc = blockIdx.x;
    int tid = threadIdx.x;  // 512

    for (int i = tid; i < 1800; i += 512) s_d2i0[i] = g_D2I0[i];

    if (tid < 450) {
        int jh = tid / 225, mk = tid % 225;
        float2 acc[8];
#pragma unroll
        for (int l = 0; l < 8; ++l) acc[l] = make_float2(0.f, 0.f);
        const float2* xp = g_xmn + (size_t)bc * 7200 + jh * 16 * 225 + mk;
        const float* dp = g_D2F + jh * 16 * 225 + mk;
#pragma unroll 4
        for (int j = 0; j < 16; ++j) {
            float2 xv = xp[j * 225];
#pragma unroll
            for (int l = 0; l < 8; ++l) {
                float d = dp[l * 7200 + j * 225];
                acc[l].x += d * xv.x;
                acc[l].y += d * xv.y;
            }
        }
#pragma unroll
        for (int l = 0; l < 8; ++l)
            s_xh2[jh * 1800 + l * 225 + mk] = acc[l];
    }
    __syncthreads();

    for (int i = tid; i < 1800; i += 512) {
        float2 a = s_xh2[i], b = s_xh2[1800 + i];
        s_xh2[i] = make_float2(a.x + b.x, a.y + b.y);
    }
    __syncthreads();

    float2* gout = g_G + (size_t)bc * 1800;
    for (int idx = tid; idx < 1800; idx += 512) {
        int l = idx / 225, nk = idx % 225;
        int n = nk / 15, k = nk % 15;
        float ax = 0.f, ay = 0.f;
        if (abs(n - 7) <= l) {
            const float* dp = s_d2i0 + l * 225 + n;
            const float2* xp = s_xh2 + l * 225 + k;
            for (int m = 7 - l; m <= 7 + l; ++m) {
                float d = dp[m * 15];
                float2 v = xp[m * 15];
                ax += d * v.x;
                ay += d * v.y;
            }
        }
        gout[idx] = make_float2(ax, ay);
    }
}

// ------------------------- k_dot: warp-per-b, fl-loop (G L2 reuse) ---------
__global__ __launch_bounds__(512) void k_dot(const float* __restrict__ w2r,
                                             const float* __restrict__ w2i) {
    int c  = blockIdx.x;      // 32
    int ft = blockIdx.y;      // 8
    int tid = threadIdx.x;    // 512
    int b = tid >> 5;         // warp = batch 0..15
    int lane = tid & 31;

    const float4* X4 = (const float4*)(g_G + ((size_t)b * 32 + c) * 1800);
#pragma unroll 2
    for (int fl = 0; fl < 8; ++fl) {
        int f = ft * 8 + fl;
        const float4* Wr4 = (const float4*)(w2r + ((size_t)c * 64 + f) * 1800);
        const float4* Wi4 = (const float4*)(w2i + ((size_t)c * 64 + f) * 1800);
        float acc = 0.f;
        for (int i = lane; i < 450; i += 32) {
            float4 g0 = X4[2 * i], g1 = X4[2 * i + 1];
            float4 wr = Wr4[i], wi = Wi4[i];
            acc += g0.x * wr.x + g0.y * wi.x + g0.z * wr.y + g0.w * wi.y
                 + g1.x * wr.z + g1.y * wi.z + g1.z * wr.w + g1.w * wi.w;
        }
#pragma unroll
        for (int o = 16; o > 0; o >>= 1)
            acc += __shfl_xor_sync(0xffffffffu, acc, o);
        if (lane == 0)
            g_partial[(c * 8 + ft) * 128 + b * 8 + fl] = acc;
    }
}

// ------------------------- head: reduce + conv1d + BN + FC -----------------
__global__ void k_head(const float* __restrict__ w3, const float* __restrict__ b3,
                       const float* __restrict__ gam, const float* __restrict__ bet,
                       const float* __restrict__ fcw, const float* __restrict__ fcb,
                       float* __restrict__ out) {
    __shared__ float s_feat[16 * 64];
    __shared__ float s_r3[16 * 570];
    __shared__ float s_mu[10], s_rstd[10];
    __shared__ float s_ps[160], s_ps2[160];
    int tid = threadIdx.x;    // 256

    for (int idx = tid; idx < 1024; idx += 256) {
        int b = idx >> 6;
        int f = idx & 63;
        int ft = f >> 3, fl = f & 7;
        float s = 0.f;
#pragma unroll
        for (int c = 0; c < 32; ++c)
            s += g_partial[(c * 8 + ft) * 128 + (b << 3) + fl];
        s_feat[b * 64 + f] = fmaxf(s, 0.f);
    }
    __syncthreads();

    for (int idx = tid; idx < 9120; idx += 256) {
        int b = idx / 570;
        int r = idx % 570;
        int o = r / 57, t = r % 57;
        float s = b3[o];
#pragma unroll
        for (int k = 0; k < 8; ++k)
            s += w3[o * 8 + k] * s_feat[b * 64 + t + k];
        s_r3[idx] = fmaxf(s, 0.f);
    }
    __syncthreads();

    if (tid < 160) {
        int o = tid >> 4, i = tid & 15;
        float s = 0.f, s2 = 0.f;
        for (int idx2 = i; idx2 < 912; idx2 += 16) {
            int b = idx2 / 57, t = idx2 % 57;
            float v = s_r3[b * 570 + o * 57 + t];
            s += v;
            s2 += v * v;
        }
        s_ps[tid] = s;
        s_ps2[tid] = s2;
    }
    __syncthreads();

    if (tid < 10) {
        float s = 0.f, s2 = 0.f;
#pragma unroll
        for (int i = 0; i < 16; ++i) {
            s += s_ps[tid * 16 + i];
            s2 += s_ps2[tid * 16 + i];
        }
        float mu = s / 912.f;
        float var = s2 / 912.f - mu * mu;
        s_mu[tid] = mu;
        s_rstd[tid] = rsqrtf(var + 1e-5f);
    }
    __syncthreads();

    for (int idx = tid; idx < 9120; idx += 256) {
        int o = (idx % 570) / 57;
        s_r3[idx] = gam[o] * (s_r3[idx] - s_mu[o]) * s_rstd[o] + bet[o];
    }
    __syncthreads();

    if (tid < 160) {
        int b = tid / 10, i = tid % 10;
        float s = fcb[i];
        const float* wr = fcw + i * 570;
        const float* xr = s_r3 + b * 570;
        for (int z = 0; z < 570; ++z) s += xr[z] * wr[z];
        out[b * 10 + i] = s;
    }
}

// ---------------------------------------------------------------------------
extern "C" void kernel_launch(void* const* d_in, const int* in_sizes, int n_in,
                              void* d_out, int out_size) {
    const float* x   = (const float*)d_in[0];
    const float* w1r = (const float*)d_in[1];
    const float* w1i = (const float*)d_in[2];
    const float* w2r = (const float*)d_in[3];
    const float* w2i = (const float*)d_in[4];
    const float* c3w = (const float*)d_in[5];
    const float* c3b = (const float*)d_in[6];
    const float* bng = (const float*)d_in[7];
    const float* bnb = (const float*)d_in[8];
    const float* fcw = (const float*)d_in[9];
    const float* fcb = (const float*)d_in[10];
    float* out = (float*)d_out;

    t_setup<<<1, 64>>>();
    t_tables<<<(646920 + 127) / 128, 128>>>();

    k_xh<<<16 * 31, 64>>>(x);
    k_main<<<8 * 32 * 32, 256>>>(w1r, w1i);
    k_G<<<512, 512>>>();
    k_dot<<<dim3(32, 8), 512>>>(w2r, w2i);
    k_head<<<1, 256>>>(c3w, c3b, bng, bnb, fcw, fcb, out);
}

// round 16
// speedup vs baseline: 1.1322x; 1.0050x over previous
#include <cuda_runtime.h>
#include <math.h>

// ---------------------------------------------------------------------------
// S2ConvNet forward pass, sm_103a.
// Shapes: B=16, F1=32, F2=64, B0=32, B1=16, B2=8, M1=31, M2=15.
// ---------------------------------------------------------------------------

#define PI_D 3.141592653589793238462643383279502884
#define TWOPI_32F 0.19634954084936207f   // 2*pi/32

// ------------------------- static device scratch ---------------------------
__device__ float  g_D1F[16 * 64 * 31];                       // [l][j][m]
__device__ __align__(16) float g_D1I[16 * 32 * 31 * 32];     // [l][j][m][n] n padded
__device__ float  g_D2F[8 * 32 * 15 * 15];                   // [l][j][m][k]
__device__ float  g_D2I0[8 * 15 * 15];                       // [l][m][n]
__device__ float2 g_xh[16 * 16 * 31];                        // [b][l][m]
__device__ __align__(16) float2 g_xmn[16 * 32 * 32 * 225];   // [b][c][j][m][k]
__device__ __align__(16) float2 g_G[16 * 32 * 1800];         // [b][c][l][n][k]
__device__ float  g_partial[32 * 8 * 128];
__device__ int    g_wedge[1496];          // packed (l<<10)|(m<<5)|n; first 204: l<8

// beta-grid precompute (incl. tan^2(beta/2))
__device__ double g_cb0[64], g_sb0[64], g_w0[64], g_ts0[64];
__device__ double g_cb1[32], g_sb1[32], g_w1[32], g_ts1[32];
__device__ double g_cb2[16], g_sb2[16], g_ts2[16];

__device__ static const double c_F[32] = {
    1.0, 1.0, 2.0, 6.0, 24.0, 120.0, 720.0, 5040.0, 40320.0, 362880.0,
    3628800.0, 39916800.0, 479001600.0, 6227020800.0, 87178291200.0,
    1307674368000.0, 20922789888000.0, 355687428096000.0, 6402373705728000.0,
    121645100408832000.0, 2432902008176640000.0, 51090942171709440000.0,
    1124000727777607680000.0, 25852016738884976640000.0,
    620448401733239439360000.0, 15511210043330985984000000.0,
    403291461126605635584000000.0, 10888869450418352160768000000.0,
    304888344611713860501504000000.0, 8841761993739701954543616000000.0,
    265252859812191058636308480000000.0, 8222838654177922817725562880000000.0
};

__device__ static const double c_R[32] = {
    0.0, 1.0, 1.0/2.0, 1.0/3.0, 1.0/4.0, 1.0/5.0, 1.0/6.0, 1.0/7.0,
    1.0/8.0, 1.0/9.0, 1.0/10.0, 1.0/11.0, 1.0/12.0, 1.0/13.0, 1.0/14.0,
    1.0/15.0, 1.0/16.0, 1.0/17.0, 1.0/18.0, 1.0/19.0, 1.0/20.0, 1.0/21.0,
    1.0/22.0, 1.0/23.0, 1.0/24.0, 1.0/25.0, 1.0/26.0, 1.0/27.0, 1.0/28.0,
    1.0/29.0, 1.0/30.0, 1.0/31.0
};

__device__ __forceinline__ double ipow_d(double x, int e) {
    double r = 1.0;
    while (e) { if (e & 1) r *= x; x *= x; e >>= 1; }
    return r;
}

__device__ double wig_fast(int l, int m, int n, double cb, double sb, double ts) {
    int kmin = max(0, m - n);
    int kmax = min(l + m, l - n);
    if (kmax < kmin) return 0.0;
    double t = sqrt(c_F[l + m] * c_F[l - m] * c_F[l + n] * c_F[l - n])
             / (c_F[kmin] * c_F[l + m - kmin] * c_F[l - n - kmin] * c_F[n - m + kmin]);
    t *= ipow_d(cb, 2 * l + m - n - 2 * kmin) * ipow_d(sb, n - m + 2 * kmin);
    if (kmin & 1) t = -t;
    double s = t;
    for (int k = kmin; k < kmax; ++k) {
        t *= -((double)((l + m - k) * (l - n - k)) *
               c_R[k + 1] * c_R[n - m + k + 1]) * ts;
        s += t;
    }
    return s;
}

// ------------------------- setup kernel ------------------------------------
__global__ void t_setup() {
    int t = threadIdx.x;   // 64
    if (t < 64) {
        double beta = PI_D * (2.0 * t + 1.0) / 128.0;
        double sb, cb;
        sincos(beta * 0.5, &sb, &cb);
        g_cb0[t] = cb; g_sb0[t] = sb;
        g_ts0[t] = (sb * sb) / (cb * cb);
        double sinb = 2.0 * sb * cb;
        double c2 = 1.0 - 2.0 * sinb * sinb;
        double prev = -sinb, cur = sinb, s = 0.0;
#pragma unroll
        for (int k = 0; k < 32; ++k) {
            s += cur * (1.0 / (2.0 * k + 1.0));
            double nx = 2.0 * c2 * cur - prev;
            prev = cur; cur = nx;
        }
        g_w0[t] = (2.0 / 32.0) * sinb * s;
    }
    if (t < 32) {
        double beta = PI_D * (2.0 * t + 1.0) / 64.0;
        double sb, cb;
        sincos(beta * 0.5, &sb, &cb);
        g_cb1[t] = cb; g_sb1[t] = sb;
        g_ts1[t] = (sb * sb) / (cb * cb);
        double sinb = 2.0 * sb * cb;
        double c2 = 1.0 - 2.0 * sinb * sinb;
        double prev = -sinb, cur = sinb, s = 0.0;
#pragma unroll
        for (int k = 0; k < 16; ++k) {
            s += cur * (1.0 / (2.0 * k + 1.0));
            double nx = 2.0 * c2 * cur - prev;
            prev = cur; cur = nx;
        }
        g_w1[t] = (2.0 / 16.0) * sinb * s;
    }
    if (t < 16) {
        double beta = PI_D * (2.0 * t + 1.0) / 32.0;
        double sb, cb;
        sincos(beta * 0.5, &sb, &cb);
        g_cb2[t] = cb; g_sb2[t] = sb;
        g_ts2[t] = (sb * sb) / (cb * cb);
        // build canonical wedge list for l = t (ordered by l so l<8 come first)
        int off = t * (t + 1) * (2 * t + 1) / 6;
        for (int mt = -t; mt <= t; ++mt) {
            int amt = mt < 0 ? -mt : mt;
            for (int nt = amt; nt <= t; ++nt)
                g_wedge[off++] = (t << 10) | ((mt + 15) << 5) | (nt + 15);
        }
    }
}

// ------------------------- merged table kernel -----------------------------
// D1F 31744 | D1I zero 507904 | D1I compact 47872 | D2F zero 57600 |
// D2F compact 6528 | D2I0 1800   => 653448
__global__ void t_tables() {
    int idx = blockIdx.x * blockDim.x + threadIdx.x;
    if (idx < 31744) {
        int l = idx / (64 * 31);
        int j = (idx / 31) % 64;
        int m = idx % 31;
        int mt = m - 15;
        float* base = g_D1F + (size_t)l * 64 * 31 + (size_t)j * 31;
        if (abs(mt) > l) { base[m] = 0.f; return; }
        if (mt < 0) return;
        float v = (float)(g_w0[j] * wig_fast(l, mt, 0, g_cb0[j], g_sb0[j], g_ts0[j]));
        base[m] = v;
        base[30 - m] = (mt & 1) ? -v : v;
        return;
    }
    idx -= 31744;
    if (idx < 507904) {                     // D1I zero-fill (invalid + padding)
        int l = idx / 31744;
        int r = idx % 31744;
        int j = r / 992;
        int m = (r / 32) % 31;
        int n = r % 32;
        int mt = m - 15, nt = n - 15;
        if (n == 31 || abs(mt) > l || abs(nt) > l)
            g_D1I[(size_t)l * 31744 + (size_t)j * 992 + m * 32 + n] = 0.f;
        return;
    }
    idx -= 507904;
    if (idx < 47872) {                      // D1I canonical compact (32 j x 1496)
        int j = idx / 1496;
        int w = g_wedge[idx % 1496];
        int l = w >> 10;
        int m = (w >> 5) & 31;
        int n = w & 31;
        int mt = m - 15, nt = n - 15;
        float* base = g_D1I + (size_t)l * 31744 + (size_t)j * 992;
        float vf = (float)((2.0 * l + 1.0) *
                           wig_fast(l, mt, nt, g_cb1[j], g_sb1[j], g_ts1[j]));
        float sv = ((m - n) & 1) ? -vf : vf;
        base[m * 32 + n] = vf;
        base[n * 32 + m] = sv;
        base[(30 - m) * 32 + (30 - n)] = sv;
        base[(30 - n) * 32 + (30 - m)] = vf;
        return;
    }
    idx -= 47872;
    if (idx < 57600) {                      // D2F zero-fill
        int l = idx / (32 * 225);
        int m = (idx / 15) % 15;
        int n = idx % 15;
        if (abs(m - 7) > l || abs(n - 7) > l) g_D2F[idx] = 0.f;
        return;
    }
    idx -= 57600;
    if (idx < 6528) {                       // D2F canonical compact (32 j x 204)
        int j = idx / 204;
        int w = g_wedge[idx % 204];         // first 204 entries: l <= 7
        int l = w >> 10;
        int mt = ((w >> 5) & 31) - 15;
        int nt = (w & 31) - 15;
        int m = mt + 7, n = nt + 7;
        float* base = g_D2F + (size_t)l * 7200 + (size_t)j * 225;
        float vf = (float)(g_w1[j] * wig_fast(l, mt, nt, g_cb1[j], g_sb1[j], g_ts1[j]));
        float sv = ((m - n) & 1) ? -vf : vf;
        base[m * 15 + n] = vf;
        base[n * 15 + m] = sv;
        base[(14 - m) * 15 + (14 - n)] = sv;
        base[(14 - n) * 15 + (14 - m)] = vf;
        return;
    }
    idx -= 6528;
    if (idx < 1800) {
        int l = idx / 225;
        int m = (idx / 15) % 15;
        int n = idx % 15;
        int mt = m - 7, nt = n - 7;
        float v = 0.f;
        if (abs(mt) <= l && abs(nt) <= l)
            v = (float)((2.0 * l + 1.0) * wig_fast(l, mt, nt, g_cb2[0], g_sb2[0], g_ts2[0]));
        g_D2I0[idx] = v;
    }
}

// ------------------------- stage A: x -> xh (4 pairs/block) ----------------
__global__ void k_xh(const float* __restrict__ x) {
    __shared__ float2 s_tw[64];
    __shared__ float2 s_xm[4][64];
    int pair = blockIdx.x * 4 + threadIdx.y;   // (b,m) pair, < 496
    int b = pair / 31;
    int m = pair % 31;
    int mt = m - 15;
    int j = threadIdx.x;   // 64
    int tid = threadIdx.y * 64 + j;

    if (tid < 64) {
        float sj, cj;
        __sincosf((float)tid * (6.2831853071795864769f / 64.f), &sj, &cj);
        s_tw[tid] = make_float2(cj, sj);
    }
    __syncthreads();

    const float* xr = x + (size_t)(b * 64 + j) * 64;
    float accx = 0.f, accy = 0.f;
#pragma unroll 8
    for (int t = 0; t < 64; ++t) {
        unsigned r = ((unsigned)(mt * t)) & 63u;
        float2 e = s_tw[r];
        float v = xr[t];
        accx += v * e.x;
        accy -= v * e.y;
    }
    s_xm[threadIdx.y][j] = make_float2(accx, accy);
    __syncthreads();

    if (j < 16) {
        int l = j;
        float ax = 0.f, ay = 0.f;
        const float* dp = g_D1F + (size_t)l * 64 * 31 + m;
        const float2* xm = s_xm[threadIdx.y];
#pragma unroll 8
        for (int jj = 0; jj < 64; ++jj) {
            float d = dp[jj * 31];
            float2 v = xm[jj];
            ax += d * v.x;
            ay += d * v.y;
        }
        g_xh[(b * 16 + l) * 31 + m] = make_float2(ax, ay);
    }
}

// ------------------------- stage B+C fused plane kernel (b-paired) ---------
__global__ __launch_bounds__(256, 3) void k_main(const float* __restrict__ w1r,
                                                 const float* __restrict__ w1i) {
    __shared__ float2 s_xh2[2 * 496];                  // 7.9 KB
    __shared__ __align__(16) float2 s_w1[16 * 32];     // 4 KB
    __shared__ __align__(16) float2 s_f2[2 * 1056];    // 16.9 KB
    __shared__ float2 s_g[31 * 32];                    // 7.9 KB
    __shared__ __align__(16) float4 s_p4[31 * 16];     // 7.9 KB
    __shared__ float  s_r016[64];

    float2* sp3 = (float2*)s_p4;

    int bx = blockIdx.x;
    int bp = bx >> 10;
    int f = (bx >> 5) & 31;
    int j = bx & 31;
    int tid = threadIdx.x;

    for (int i = tid; i < 992; i += 256)
        s_xh2[i] = g_xh[(2 * bp) * 496 + i];
    for (int i = tid; i < 496; i += 256) {
        int l = i / 31, n = i % 31;
        s_w1[l * 32 + n] = make_float2(w1r[f * 496 + i], w1i[f * 496 + i]);
    }
    if (tid < 16) s_w1[tid * 32 + 31] = make_float2(0.f, 0.f);
    __syncthreads();

    // step 1 (both planes)
    if (tid < 248) {
        int m = tid >> 3, ng = tid & 7, n0 = ng * 4;
        int am = abs(m - 15);
        int nhi = n0 + 3;
        int anmin = (nhi < 15) ? (15 - nhi) : ((n0 > 15) ? (n0 - 15) : 0);
        int l0 = max(am, anmin);
        float ax[2][4] = {{0.f, 0.f, 0.f, 0.f}, {0.f, 0.f, 0.f, 0.f}};
        float ay[2][4] = {{0.f, 0.f, 0.f, 0.f}, {0.f, 0.f, 0.f, 0.f}};
        const float4* dp4 = (const float4*)(g_D1I + (size_t)j * 992 + m * 32 + n0);
        for (int l = l0; l < 16; ++l) {
            float4 d = dp4[l * 7936];
            float2 aA = s_xh2[l * 31 + m];
            float2 aB = s_xh2[496 + l * 31 + m];
            float4 wA = *(const float4*)(s_w1 + l * 32 + n0);
            float4 wB = *(const float4*)(s_w1 + l * 32 + n0 + 2);
            float wx[4] = {wA.x, wA.z, wB.x, wB.z};
            float wy[4] = {wA.y, wA.w, wB.y, wB.w};
            float dv[4] = {d.x, d.y, d.z, d.w};
#pragma unroll
            for (int k = 0; k < 4; ++k) {
                float tr = aA.x * wx[k] + aA.y * wy[k];
                float ti = aA.y * wx[k] - aA.x * wy[k];
                ax[0][k] += dv[k] * tr; ay[0][k] += dv[k] * ti;
                tr = aB.x * wx[k] + aB.y * wy[k];
                ti = aB.y * wx[k] - aB.x * wy[k];
                ax[1][k] += dv[k] * tr; ay[1][k] += dv[k] * ti;
            }
        }
#pragma unroll
        for (int bb = 0; bb < 2; ++bb) {
            float2* sf = s_f2 + bb * 1056;
            *(float4*)(sf + m * 34 + n0)     = make_float4(ax[bb][0], ay[bb][0], ax[bb][1], ay[bb][1]);
            *(float4*)(sf + m * 34 + n0 + 2) = make_float4(ax[bb][2], ay[bb][2], ax[bb][3], ay[bb][3]);
        }
    }
    __syncthreads();

    for (int bb = 0; bb < 2; ++bb) {
        float2* s_f = s_f2 + bb * 1056;
        float2* sp4 = s_f;
        float2* s_u = s_f + 560;

        // pass A: pair f over nt
        for (int i = tid; i < 496; i += 256) {
            int m = i >> 4, nt = i & 15;
            float4 v;
            if (nt == 0) {
                float2 c = s_f[m * 34 + 15];
                v = make_float4(c.x, c.y, 0.f, 0.f);
            } else {
                float2 fp = s_f[m * 34 + 15 + nt];
                float2 fm = s_f[m * 34 + 15 - nt];
                v = make_float4(fp.x + fm.x, fp.y + fm.y, fp.x - fm.x, fp.y - fm.y);
            }
            s_p4[m * 16 + nt] = v;
        }
        __syncthreads();

        // step 2: g[m,q], 4-way q blocking
        if (tid < 248) {
            int m = tid >> 3, q0 = tid & 7;
            float2 S, E;
            __sincosf((float)q0 * TWOPI_32F, &S.y, &S.x);
            E = S;
            const float4* prow = s_p4 + m * 16;
            float4 c0 = prow[0];
            float a0x = c0.x, a0y = c0.y, a1x = c0.x, a1y = c0.y;
            float a2x = c0.x, a2y = c0.y, a3x = c0.x, a3y = c0.y;
            int nt = 1;
#define S2P(PP)                                                              \
            {                                                                \
                float4 pr = prow[nt];                                        \
                float p1 = E.x * pr.x, p2 = E.y * pr.w;                      \
                float p3 = E.x * pr.y, p4 = E.y * pr.z;                      \
                float tx = p1 - p2, ty = p3 + p4;                            \
                a0x += tx; a0y += ty;                                        \
                if (PP == 0) { a1x += tx; a1y += ty; a2x += tx; a2y += ty;   \
                               a3x += tx; a3y += ty; }                       \
                if (PP == 2) { a1x -= tx; a1y -= ty; a2x += tx; a2y += ty;   \
                               a3x -= tx; a3y -= ty; }                       \
                if (PP == 1 || PP == 3) {                                    \
                    float r1 = E.y * pr.x, r2 = E.x * pr.w;                  \
                    float r3 = E.y * pr.y, r4 = E.x * pr.z;                  \
                    float ux = r1 + r2, uy = r3 - r4;                        \
                    if (PP == 1) { a1x -= ux; a1y -= uy; a2x -= tx;          \
                                   a2y -= ty; a3x += ux; a3y += uy; }        \
                    if (PP == 3) { a1x += ux; a1y += uy; a2x -= tx;          \
                                   a2y -= ty; a3x -= ux; a3y -= uy; }        \
                }                                                            \
                float ex = E.x * S.x - E.y * S.y;                            \
                E.y = E.x * S.y + E.y * S.x;                                 \
                E.x = ex;                                                    \
                ++nt;                                                        \
            }
#pragma unroll
            for (int g4 = 0; g4 < 3; ++g4) {
                S2P(1) S2P(2) S2P(3) S2P(0)
            }
            S2P(1) S2P(2) S2P(3)
#undef S2P
            s_g[m * 32 + q0]      = make_float2(a0x, a0y);
            s_g[m * 32 + q0 + 8]  = make_float2(a1x, a1y);
            s_g[m * 32 + q0 + 16] = make_float2(a2x, a2y);
            s_g[m * 32 + q0 + 24] = make_float2(a3x, a3y);
        }
        __syncthreads();

        // pass B: pair g over mt
        for (int i = tid; i < 480; i += 256) {
            int mt = 1 + (i >> 5), q = i & 31;
            float2 gp = s_g[(15 + mt) * 32 + q];
            float2 gm = s_g[(15 - mt) * 32 + q];
            sp3[(mt - 1) * 32 + q] = make_float2(gp.x + gm.x, gp.y - gm.y);
        }
        __syncthreads();

        // step 3 + in-warp pass C
        {
            int q = tid & 31, p0 = tid >> 5;
            float2 S, E;
            __sincosf((float)p0 * TWOPI_32F, &S.y, &S.x);
            E = S;
            float c = s_g[15 * 32 + q].x;
            float a0 = c, a1 = c, a2 = c, a3 = c;
            const float2* pcol = sp3 + q;
            int mt = 1;
#define S3P(PP)                                                              \
            {                                                                \
                float2 v = pcol[(mt - 1) * 32];                              \
                float u1 = E.x * v.x, u2 = E.y * v.y;                        \
                float tx = u1 - u2;                                          \
                a0 += tx;                                                    \
                if (PP == 0) { a1 += tx; a2 += tx; a3 += tx; }               \
                if (PP == 2) { a1 -= tx; a2 += tx; a3 -= tx; }               \
                if (PP == 1 || PP == 3) {                                    \
                    float v1 = E.y * v.x, v2 = E.x * v.y;                    \
                    float ux = v1 + v2;                                      \
                    if (PP == 1) { a1 -= ux; a2 -= tx; a3 += ux; }           \
                    if (PP == 3) { a1 += ux; a2 -= tx; a3 -= ux; }           \
                }                                                            \
                float ex = E.x * S.x - E.y * S.y;                            \
                E.y = E.x * S.y + E.y * S.x;                                 \
                E.x = ex;                                                    \
                ++mt;                                                        \
            }
#pragma unroll
            for (int g4 = 0; g4 < 3; ++g4) {
                S3P(1) S3P(2) S3P(3) S3P(0)
            }
            S3P(1) S3P(2) S3P(3)
#undef S3P
            a0 = fmaxf(a0, 0.f);
            a1 = fmaxf(a1, 0.f);
            a2 = fmaxf(a2, 0.f);
            a3 = fmaxf(a3, 0.f);
            int src = (32 - q) & 31;
            float b0 = __shfl_sync(0xffffffffu, a0, src);
            float b1 = __shfl_sync(0xffffffffu, a1, src);
            float b2 = __shfl_sync(0xffffffffu, a2, src);
            float b3 = __shfl_sync(0xffffffffu, a3, src);
            __syncthreads();
            if (q >= 1 && q <= 15) {
                int qm1 = q - 1;
                sp4[p0 * 17 + qm1]        = make_float2(a0 + b0, a0 - b0);
                sp4[(p0 + 8) * 17 + qm1]  = make_float2(a1 + b1, a1 - b1);
                sp4[(p0 + 16) * 17 + qm1] = make_float2(a2 + b2, a2 - b2);
                sp4[(p0 + 24) * 17 + qm1] = make_float2(a3 + b3, a3 - b3);
            } else if (q == 0) {
                s_r016[p0]      = a0;
                s_r016[p0 + 8]  = a1;
                s_r016[p0 + 16] = a2;
                s_r016[p0 + 24] = a3;
            } else if (q == 16) {
                s_r016[32 + p0]      = a0;
                s_r016[32 + p0 + 8]  = a1;
                s_r016[32 + p0 + 16] = a2;
                s_r016[32 + p0 + 24] = a3;
            }
        }
        __syncthreads();

        // step 4
        {
            int p = tid >> 3, d = tid & 7;
            float2 W1;
            __sincosf((float)d * TWOPI_32F, &W1.y, &W1.x);
            W1.y = -W1.y;
            float2 W = W1;
            float r0 = s_r016[p];
            float r16 = s_r016[32 + p];
            float axv = r0 + ((d & 1) ? -r16 : r16);
            float ayv = 0.f;
            const float2* sd = sp4 + p * 17;
#pragma unroll
            for (int q = 1; q <= 15; ++q) {
                float2 v = sd[q - 1];
                axv += v.x * W.x;
                ayv += v.y * W.y;
                float wx = W.x * W1.x - W.y * W1.y;
                W.y = W.x * W1.y + W.y * W1.x;
                W.x = wx;
            }
            s_u[p * 8 + d] = make_float2(axv, ayv);
        }
        __syncthreads();

        // step 5 (Hermitian half)
        if (tid < 120) {
            int m2 = tid >> 3, d = tid & 7;
            int n2 = 7 + d;
            int mt = m2 - 7;
            float2 W = make_float2(1.f, 0.f), S5;
            {
                float ss, cc;
                __sincosf((float)mt * TWOPI_32F, &ss, &cc);
                S5 = make_float2(cc, -ss);
            }
            float axv = 0.f, ayv = 0.f;
            const float2* ucol = s_u + d;
#pragma unroll
            for (int p = 0; p < 32; ++p) {
                float2 u = ucol[p * 8];
                axv += u.x * W.x - u.y * W.y;
                ayv += u.x * W.y + u.y * W.x;
                float wx = W.x * S5.x - W.y * S5.y;
                W.y = W.x * S5.y + W.y * S5.x;
                W.x = wx;
            }
            size_t plane = (size_t)(2 * bp + bb) * 1024 + f * 32 + j;
            float2* outp = g_xmn + plane * 225;
            outp[m2 * 15 + n2] = make_float2(axv, ayv);
            if (d > 0)
                outp[(14 - m2) * 15 + (14 - n2)] = make_float2(axv, -ayv);
        }
        __syncthreads();
    }
}

// ------------------------- k_G: xmn -> xh2 -> G (per (b,c)) ----------------
__global__ __launch_bounds__(512) void k_G() {
    __shared__ float2 s_xh2[2 * 8 * 225];
    __shared__ float  s_d2i0[1800];
    int bc = blockIdx.x;
    int tid = threadIdx.x;  // 512

    for (int i = tid; i < 1800; i += 512) s_d2i0[i] = g_D2I0[i];

    if (tid < 450) {
        int jh = tid / 225, mk = tid % 225;
        float2 acc[8];
#pragma unroll
        for (int l = 0; l < 8; ++l) acc[l] = make_float2(0.f, 0.f);
        const float2* xp = g_xmn + (size_t)bc * 7200 + jh * 16 * 225 + mk;
        const float* dp = g_D2F + jh * 16 * 225 + mk;
#pragma unroll 4
        for (int j = 0; j < 16; ++j) {
            float2 xv = xp[j * 225];
#pragma unroll
            for (int l = 0; l < 8; ++l) {
                float d = dp[l * 7200 + j * 225];
                acc[l].x += d * xv.x;
                acc[l].y += d * xv.y;
            }
        }
#pragma unroll
        for (int l = 0; l < 8; ++l)
            s_xh2[jh * 1800 + l * 225 + mk] = acc[l];
    }
    __syncthreads();

    for (int i = tid; i < 1800; i += 512) {
        float2 a = s_xh2[i], b = s_xh2[1800 + i];
        s_xh2[i] = make_float2(a.x + b.x, a.y + b.y);
    }
    __syncthreads();

    float2* gout = g_G + (size_t)bc * 1800;
    for (int idx = tid; idx < 1800; idx += 512) {
        int l = idx / 225, nk = idx % 225;
        int n = nk / 15, k = nk % 15;
        float ax = 0.f, ay = 0.f;
        if (abs(n - 7) <= l) {
            const float* dp = s_d2i0 + l * 225 + n;
            const float2* xp = s_xh2 + l * 225 + k;
            for (int m = 7 - l; m <= 7 + l; ++m) {
                float d = dp[m * 15];
                float2 v = xp[m * 15];
                ax += d * v.x;
                ay += d * v.y;
            }
        }
        gout[idx] = make_float2(ax, ay);
    }
}

// ------------------------- k_dot: warp-per-b, fl-loop (G L2 reuse) ---------
__global__ __launch_bounds__(512) void k_dot(const float* __restrict__ w2r,
                                             const float* __restrict__ w2i) {
    int c  = blockIdx.x;      // 32
    int ft = blockIdx.y;      // 8
    int tid = threadIdx.x;    // 512
    int b = tid >> 5;         // warp = batch 0..15
    int lane = tid & 31;

    const float4* X4 = (const float4*)(g_G + ((size_t)b * 32 + c) * 1800);
#pragma unroll 2
    for (int fl = 0; fl < 8; ++fl) {
        int f = ft * 8 + fl;
        const float4* Wr4 = (const float4*)(w2r + ((size_t)c * 64 + f) * 1800);
        const float4* Wi4 = (const float4*)(w2i + ((size_t)c * 64 + f) * 1800);
        float acc = 0.f;
        for (int i = lane; i < 450; i += 32) {
            float4 g0 = X4[2 * i], g1 = X4[2 * i + 1];
            float4 wr = Wr4[i], wi = Wi4[i];
            acc += g0.x * wr.x + g0.y * wi.x + g0.z * wr.y + g0.w * wi.y
                 + g1.x * wr.z + g1.y * wi.z + g1.z * wr.w + g1.w * wi.w;
        }
#pragma unroll
        for (int o = 16; o > 0; o >>= 1)
            acc += __shfl_xor_sync(0xffffffffu, acc, o);
        if (lane == 0)
            g_partial[(c * 8 + ft) * 128 + b * 8 + fl] = acc;
    }
}

// ------------------------- head: reduce + conv1d + BN + FC -----------------
__global__ void k_head(const float* __restrict__ w3, const float* __restrict__ b3,
                       const float* __restrict__ gam, const float* __restrict__ bet,
                       const float* __restrict__ fcw, const float* __restrict__ fcb,
                       float* __restrict__ out) {
    __shared__ float s_feat[16 * 64];
    __shared__ float s_r3[16 * 570];
    __shared__ float s_mu[10], s_rstd[10];
    __shared__ float s_ps[160], s_ps2[160];
    int tid = threadIdx.x;    // 256

    for (int idx = tid; idx < 1024; idx += 256) {
        int b = idx >> 6;
        int f = idx & 63;
        int ft = f >> 3, fl = f & 7;
        float s = 0.f;
#pragma unroll
        for (int c = 0; c < 32; ++c)
            s += g_partial[(c * 8 + ft) * 128 + (b << 3) + fl];
        s_feat[b * 64 + f] = fmaxf(s, 0.f);
    }
    __syncthreads();

    for (int idx = tid; idx < 9120; idx += 256) {
        int b = idx / 570;
        int r = idx % 570;
        int o = r / 57, t = r % 57;
        float s = b3[o];
#pragma unroll
        for (int k = 0; k < 8; ++k)
            s += w3[o * 8 + k] * s_feat[b * 64 + t + k];
        s_r3[idx] = fmaxf(s, 0.f);
    }
    __syncthreads();

    if (tid < 160) {
        int o = tid >> 4, i = tid & 15;
        float s = 0.f, s2 = 0.f;
        for (int idx2 = i; idx2 < 912; idx2 += 16) {
            int b = idx2 / 57, t = idx2 % 57;
            float v = s_r3[b * 570 + o * 57 + t];
            s += v;
            s2 += v * v;
        }
        s_ps[tid] = s;
        s_ps2[tid] = s2;
    }
    __syncthreads();

    if (tid < 10) {
        float s = 0.f, s2 = 0.f;
#pragma unroll
        for (int i = 0; i < 16; ++i) {
            s += s_ps[tid * 16 + i];
            s2 += s_ps2[tid * 16 + i];
        }
        float mu = s / 912.f;
        float var = s2 / 912.f - mu * mu;
        s_mu[tid] = mu;
        s_rstd[tid] = rsqrtf(var + 1e-5f);
    }
    __syncthreads();

    for (int idx = tid; idx < 9120; idx += 256) {
        int o = (idx % 570) / 57;
        s_r3[idx] = gam[o] * (s_r3[idx] - s_mu[o]) * s_rstd[o] + bet[o];
    }
    __syncthreads();

    if (tid < 160) {
        int b = tid / 10, i = tid % 10;
        float s = fcb[i];
        const float* wr = fcw + i * 570;
        const float* xr = s_r3 + b * 570;
        for (int z = 0; z < 570; ++z) s += xr[z] * wr[z];
        out[b * 10 + i] = s;
    }
}

// ---------------------------------------------------------------------------
extern "C" void kernel_launch(void* const* d_in, const int* in_sizes, int n_in,
                              void* d_out, int out_size) {
    const float* x   = (const float*)d_in[0];
    const float* w1r = (const float*)d_in[1];
    const float* w1i = (const float*)d_in[2];
    const float* w2r = (const float*)d_in[3];
    const float* w2i = (const float*)d_in[4];
    const float* c3w = (const float*)d_in[5];
    const float* c3b = (const float*)d_in[6];
    const float* bng = (const float*)d_in[7];
    const float* bnb = (const float*)d_in[8];
    const float* fcw = (const float*)d_in[9];
    const float* fcb = (const float*)d_in[10];
    float* out = (float*)d_out;

    t_setup<<<1, 64>>>();
    t_tables<<<(653448 + 127) / 128, 128>>>();

    k_xh<<<124, dim3(64, 4)>>>(x);
    k_main<<<8 * 32 * 32, 256>>>(w1r, w1i);
    k_G<<<512, 512>>>();
    k_dot<<<dim3(32, 8), 512>>>(w2r, w2i);
    k_head<<<1, 256>>>(c3w, c3b, bng, bnb, fcw, fcb, out);
}

// round 17
// speedup vs baseline: 1.2093x; 1.0682x over previous
#include <cuda_runtime.h>
#include <math.h>

// ---------------------------------------------------------------------------
// S2ConvNet forward pass, sm_103a.
// Shapes: B=16, F1=32, F2=64, B0=32, B1=16, B2=8, M1=31, M2=15.
// ---------------------------------------------------------------------------

#define PI_D 3.141592653589793238462643383279502884
#define TWOPI_32F 0.19634954084936207f   // 2*pi/32

// ------------------------- static device scratch ---------------------------
__device__ float  g_D1F[16 * 64 * 31];                       // [l][j][m]
__device__ __align__(16) float g_D1I[16 * 32 * 31 * 32];     // [l][j][m][n] n padded
__device__ float  g_D2F[8 * 32 * 15 * 15];                   // [l][j][m][k]
__device__ float  g_D2I0[8 * 15 * 15];                       // [l][m][n]
__device__ float2 g_xh[16 * 16 * 31];                        // [b][l][m]
__device__ __align__(16) float2 g_xmn[16 * 32 * 32 * 225];   // [b][c][j][m][k]
__device__ __align__(16) float2 g_G[16 * 32 * 1800];         // [b][c][l][n][k]
__device__ float  g_partial[32 * 8 * 128];
__device__ int    g_wedge[1496];          // packed (l<<10)|(m<<5)|n; first 204: l<8

// beta-grid precompute (incl. tan^2(beta/2))
__device__ double g_cb0[64], g_sb0[64], g_w0[64], g_ts0[64];
__device__ double g_cb1[32], g_sb1[32], g_w1[32], g_ts1[32];
__device__ double g_cb2[16], g_sb2[16], g_ts2[16];

__device__ static const double c_F[32] = {
    1.0, 1.0, 2.0, 6.0, 24.0, 120.0, 720.0, 5040.0, 40320.0, 362880.0,
    3628800.0, 39916800.0, 479001600.0, 6227020800.0, 87178291200.0,
    1307674368000.0, 20922789888000.0, 355687428096000.0, 6402373705728000.0,
    121645100408832000.0, 2432902008176640000.0, 51090942171709440000.0,
    1124000727777607680000.0, 25852016738884976640000.0,
    620448401733239439360000.0, 15511210043330985984000000.0,
    403291461126605635584000000.0, 10888869450418352160768000000.0,
    304888344611713860501504000000.0, 8841761993739701954543616000000.0,
    265252859812191058636308480000000.0, 8222838654177922817725562880000000.0
};

__device__ static const double c_R[32] = {
    0.0, 1.0, 1.0/2.0, 1.0/3.0, 1.0/4.0, 1.0/5.0, 1.0/6.0, 1.0/7.0,
    1.0/8.0, 1.0/9.0, 1.0/10.0, 1.0/11.0, 1.0/12.0, 1.0/13.0, 1.0/14.0,
    1.0/15.0, 1.0/16.0, 1.0/17.0, 1.0/18.0, 1.0/19.0, 1.0/20.0, 1.0/21.0,
    1.0/22.0, 1.0/23.0, 1.0/24.0, 1.0/25.0, 1.0/26.0, 1.0/27.0, 1.0/28.0,
    1.0/29.0, 1.0/30.0, 1.0/31.0
};

__device__ __forceinline__ double ipow_d(double x, int e) {
    double r = 1.0;
    while (e) { if (e & 1) r *= x; x *= x; e >>= 1; }
    return r;
}

__device__ double wig_fast(int l, int m, int n, double cb, double sb, double ts) {
    int kmin = max(0, m - n);
    int kmax = min(l + m, l - n);
    if (kmax < kmin) return 0.0;
    double t = sqrt(c_F[l + m] * c_F[l - m] * c_F[l + n] * c_F[l - n])
             / (c_F[kmin] * c_F[l + m - kmin] * c_F[l - n - kmin] * c_F[n - m + kmin]);
    t *= ipow_d(cb, 2 * l + m - n - 2 * kmin) * ipow_d(sb, n - m + 2 * kmin);
    if (kmin & 1) t = -t;
    double s = t;
    for (int k = kmin; k < kmax; ++k) {
        t *= -((double)((l + m - k) * (l - n - k)) *
               c_R[k + 1] * c_R[n - m + k + 1]) * ts;
        s += t;
    }
    return s;
}

// ------------------------- setup kernel ------------------------------------
__global__ void t_setup() {
    int t = threadIdx.x;   // 64
    if (t < 64) {
        double beta = PI_D * (2.0 * t + 1.0) / 128.0;
        double sb, cb;
        sincos(beta * 0.5, &sb, &cb);
        g_cb0[t] = cb; g_sb0[t] = sb;
        g_ts0[t] = (sb * sb) / (cb * cb);
        double sinb = 2.0 * sb * cb;
        double c2 = 1.0 - 2.0 * sinb * sinb;
        double prev = -sinb, cur = sinb, s = 0.0;
#pragma unroll
        for (int k = 0; k < 32; ++k) {
            s += cur * (1.0 / (2.0 * k + 1.0));
            double nx = 2.0 * c2 * cur - prev;
            prev = cur; cur = nx;
        }
        g_w0[t] = (2.0 / 32.0) * sinb * s;
    }
    if (t < 32) {
        double beta = PI_D * (2.0 * t + 1.0) / 64.0;
        double sb, cb;
        sincos(beta * 0.5, &sb, &cb);
        g_cb1[t] = cb; g_sb1[t] = sb;
        g_ts1[t] = (sb * sb) / (cb * cb);
        double sinb = 2.0 * sb * cb;
        double c2 = 1.0 - 2.0 * sinb * sinb;
        double prev = -sinb, cur = sinb, s = 0.0;
#pragma unroll
        for (int k = 0; k < 16; ++k) {
            s += cur * (1.0 / (2.0 * k + 1.0));
            double nx = 2.0 * c2 * cur - prev;
            prev = cur; cur = nx;
        }
        g_w1[t] = (2.0 / 16.0) * sinb * s;
    }
    if (t < 16) {
        double beta = PI_D * (2.0 * t + 1.0) / 32.0;
        double sb, cb;
        sincos(beta * 0.5, &sb, &cb);
        g_cb2[t] = cb; g_sb2[t] = sb;
        g_ts2[t] = (sb * sb) / (cb * cb);
        int off = t * (t + 1) * (2 * t + 1) / 6;
        for (int mt = -t; mt <= t; ++mt) {
            int amt = mt < 0 ? -mt : mt;
            for (int nt = amt; nt <= t; ++nt)
                g_wedge[off++] = (t << 10) | ((mt + 15) << 5) | (nt + 15);
        }
    }
}

// ------------------------- merged table kernel -----------------------------
// D1F 31744 | D1I zero 507904 | D1I compact 47872 | D2F zero 57600 |
// D2F compact 6528 | D2I0 1800   => 653448
__global__ void t_tables() {
    int idx = blockIdx.x * blockDim.x + threadIdx.x;
    if (idx < 31744) {
        int l = idx / (64 * 31);
        int j = (idx / 31) % 64;
        int m = idx % 31;
        int mt = m - 15;
        float* base = g_D1F + (size_t)l * 64 * 31 + (size_t)j * 31;
        if (abs(mt) > l) { base[m] = 0.f; return; }
        if (mt < 0) return;
        float v = (float)(g_w0[j] * wig_fast(l, mt, 0, g_cb0[j], g_sb0[j], g_ts0[j]));
        base[m] = v;
        base[30 - m] = (mt & 1) ? -v : v;
        return;
    }
    idx -= 31744;
    if (idx < 507904) {
        int l = idx / 31744;
        int r = idx % 31744;
        int j = r / 992;
        int m = (r / 32) % 31;
        int n = r % 32;
        int mt = m - 15, nt = n - 15;
        if (n == 31 || abs(mt) > l || abs(nt) > l)
            g_D1I[(size_t)l * 31744 + (size_t)j * 992 + m * 32 + n] = 0.f;
        return;
    }
    idx -= 507904;
    if (idx < 47872) {
        int j = idx / 1496;
        int w = g_wedge[idx % 1496];
        int l = w >> 10;
        int m = (w >> 5) & 31;
        int n = w & 31;
        int mt = m - 15, nt = n - 15;
        float* base = g_D1I + (size_t)l * 31744 + (size_t)j * 992;
        float vf = (float)((2.0 * l + 1.0) *
                           wig_fast(l, mt, nt, g_cb1[j], g_sb1[j], g_ts1[j]));
        float sv = ((m - n) & 1) ? -vf : vf;
        base[m * 32 + n] = vf;
        base[n * 32 + m] = sv;
        base[(30 - m) * 32 + (30 - n)] = sv;
        base[(30 - n) * 32 + (30 - m)] = vf;
        return;
    }
    idx -= 47872;
    if (idx < 57600) {
        int l = idx / (32 * 225);
        int m = (idx / 15) % 15;
        int n = idx % 15;
        if (abs(m - 7) > l || abs(n - 7) > l) g_D2F[idx] = 0.f;
        return;
    }
    idx -= 57600;
    if (idx < 6528) {
        int j = idx / 204;
        int w = g_wedge[idx % 204];
        int l = w >> 10;
        int mt = ((w >> 5) & 31) - 15;
        int nt = (w & 31) - 15;
        int m = mt + 7, n = nt + 7;
        float* base = g_D2F + (size_t)l * 7200 + (size_t)j * 225;
        float vf = (float)(g_w1[j] * wig_fast(l, mt, nt, g_cb1[j], g_sb1[j], g_ts1[j]));
        float sv = ((m - n) & 1) ? -vf : vf;
        base[m * 15 + n] = vf;
        base[n * 15 + m] = sv;
        base[(14 - m) * 15 + (14 - n)] = sv;
        base[(14 - n) * 15 + (14 - m)] = vf;
        return;
    }
    idx -= 6528;
    if (idx < 1800) {
        int l = idx / 225;
        int m = (idx / 15) % 15;
        int n = idx % 15;
        int mt = m - 7, nt = n - 7;
        float v = 0.f;
        if (abs(mt) <= l && abs(nt) <= l)
            v = (float)((2.0 * l + 1.0) * wig_fast(l, mt, nt, g_cb2[0], g_sb2[0], g_ts2[0]));
        g_D2I0[idx] = v;
    }
}

// ------------------------- stage A: x -> xh (4 pairs/block) ----------------
__global__ void k_xh(const float* __restrict__ x) {
    __shared__ float2 s_tw[64];
    __shared__ float2 s_xm[4][64];
    int pair = blockIdx.x * 4 + threadIdx.y;
    int b = pair / 31;
    int m = pair % 31;
    int mt = m - 15;
    int j = threadIdx.x;   // 64
    int tid = threadIdx.y * 64 + j;

    if (tid < 64) {
        float sj, cj;
        __sincosf((float)tid * (6.2831853071795864769f / 64.f), &sj, &cj);
        s_tw[tid] = make_float2(cj, sj);
    }
    __syncthreads();

    const float* xr = x + (size_t)(b * 64 + j) * 64;
    float accx = 0.f, accy = 0.f;
#pragma unroll 8
    for (int t = 0; t < 64; ++t) {
        unsigned r = ((unsigned)(mt * t)) & 63u;
        float2 e = s_tw[r];
        float v = xr[t];
        accx += v * e.x;
        accy -= v * e.y;
    }
    s_xm[threadIdx.y][j] = make_float2(accx, accy);
    __syncthreads();

    if (j < 16) {
        int l = j;
        float ax = 0.f, ay = 0.f;
        const float* dp = g_D1F + (size_t)l * 64 * 31 + m;
        const float2* xm = s_xm[threadIdx.y];
#pragma unroll 8
        for (int jj = 0; jj < 64; ++jj) {
            float d = dp[jj * 31];
            float2 v = xm[jj];
            ax += d * v.x;
            ay += d * v.y;
        }
        g_xh[(b * 16 + l) * 31 + m] = make_float2(ax, ay);
    }
}

// ------------------------- stage B+C fused plane kernel (b-paired) ---------
__global__ __launch_bounds__(256, 3) void k_main(const float* __restrict__ w1r,
                                                 const float* __restrict__ w1i) {
    __shared__ float2 s_xh2[2 * 496];                  // 7.9 KB
    __shared__ __align__(16) float2 s_w1[16 * 32];     // 4 KB
    __shared__ __align__(16) float2 s_f2[2 * 1056];    // 16.9 KB
    __shared__ float2 s_g[31 * 32];                    // 7.9 KB
    __shared__ __align__(16) float4 s_p4[31 * 16];     // 7.9 KB
    __shared__ float  s_r016[64];

    float2* sp3 = (float2*)s_p4;

    int bx = blockIdx.x;
    int bp = bx >> 10;
    int f = (bx >> 5) & 31;
    int j = bx & 31;
    int tid = threadIdx.x;

    for (int i = tid; i < 992; i += 256)
        s_xh2[i] = g_xh[(2 * bp) * 496 + i];
    for (int i = tid; i < 496; i += 256) {
        int l = i / 31, n = i % 31;
        s_w1[l * 32 + n] = make_float2(w1r[f * 496 + i], w1i[f * 496 + i]);
    }
    if (tid < 16) s_w1[tid * 32 + 31] = make_float2(0.f, 0.f);
    __syncthreads();

    // step 1 (both planes)
    if (tid < 248) {
        int m = tid >> 3, ng = tid & 7, n0 = ng * 4;
        int am = abs(m - 15);
        int nhi = n0 + 3;
        int anmin = (nhi < 15) ? (15 - nhi) : ((n0 > 15) ? (n0 - 15) : 0);
        int l0 = max(am, anmin);
        float ax[2][4] = {{0.f, 0.f, 0.f, 0.f}, {0.f, 0.f, 0.f, 0.f}};
        float ay[2][4] = {{0.f, 0.f, 0.f, 0.f}, {0.f, 0.f, 0.f, 0.f}};
        const float4* dp4 = (const float4*)(g_D1I + (size_t)j * 992 + m * 32 + n0);
        for (int l = l0; l < 16; ++l) {
            float4 d = dp4[l * 7936];
            float2 aA = s_xh2[l * 31 + m];
            float2 aB = s_xh2[496 + l * 31 + m];
            float4 wA = *(const float4*)(s_w1 + l * 32 + n0);
            float4 wB = *(const float4*)(s_w1 + l * 32 + n0 + 2);
            float wx[4] = {wA.x, wA.z, wB.x, wB.z};
            float wy[4] = {wA.y, wA.w, wB.y, wB.w};
            float dv[4] = {d.x, d.y, d.z, d.w};
#pragma unroll
            for (int k = 0; k < 4; ++k) {
                float tr = aA.x * wx[k] + aA.y * wy[k];
                float ti = aA.y * wx[k] - aA.x * wy[k];
                ax[0][k] += dv[k] * tr; ay[0][k] += dv[k] * ti;
                tr = aB.x * wx[k] + aB.y * wy[k];
                ti = aB.y * wx[k] - aB.x * wy[k];
                ax[1][k] += dv[k] * tr; ay[1][k] += dv[k] * ti;
            }
        }
#pragma unroll
        for (int bb = 0; bb < 2; ++bb) {
            float2* sf = s_f2 + bb * 1056;
            *(float4*)(sf + m * 34 + n0)     = make_float4(ax[bb][0], ay[bb][0], ax[bb][1], ay[bb][1]);
            *(float4*)(sf + m * 34 + n0 + 2) = make_float4(ax[bb][2], ay[bb][2], ax[bb][3], ay[bb][3]);
        }
    }
    __syncthreads();

    for (int bb = 0; bb < 2; ++bb) {
        float2* s_f = s_f2 + bb * 1056;
        float2* sp4 = s_f;
        float2* s_u = s_f + 560;

        // pass A: pair f over nt
        for (int i = tid; i < 496; i += 256) {
            int m = i >> 4, nt = i & 15;
            float4 v;
            if (nt == 0) {
                float2 c = s_f[m * 34 + 15];
                v = make_float4(c.x, c.y, 0.f, 0.f);
            } else {
                float2 fp = s_f[m * 34 + 15 + nt];
                float2 fm = s_f[m * 34 + 15 - nt];
                v = make_float4(fp.x + fm.x, fp.y + fm.y, fp.x - fm.x, fp.y - fm.y);
            }
            s_p4[m * 16 + nt] = v;
        }
        __syncthreads();

        // step 2: g[m,q], 4-way q blocking
        if (tid < 248) {
            int m = tid >> 3, q0 = tid & 7;
            float2 S, E;
            __sincosf((float)q0 * TWOPI_32F, &S.y, &S.x);
            E = S;
            const float4* prow = s_p4 + m * 16;
            float4 c0 = prow[0];
            float a0x = c0.x, a0y = c0.y, a1x = c0.x, a1y = c0.y;
            float a2x = c0.x, a2y = c0.y, a3x = c0.x, a3y = c0.y;
            int nt = 1;
#define S2P(PP)                                                              \
            {                                                                \
                float4 pr = prow[nt];                                        \
                float p1 = E.x * pr.x, p2 = E.y * pr.w;                      \
                float p3 = E.x * pr.y, p4 = E.y * pr.z;                      \
                float tx = p1 - p2, ty = p3 + p4;                            \
                a0x += tx; a0y += ty;                                        \
                if (PP == 0) { a1x += tx; a1y += ty; a2x += tx; a2y += ty;   \
                               a3x += tx; a3y += ty; }                       \
                if (PP == 2) { a1x -= tx; a1y -= ty; a2x += tx; a2y += ty;   \
                               a3x -= tx; a3y -= ty; }                       \
                if (PP == 1 || PP == 3) {                                    \
                    float r1 = E.y * pr.x, r2 = E.x * pr.w;                  \
                    float r3 = E.y * pr.y, r4 = E.x * pr.z;                  \
                    float ux = r1 + r2, uy = r3 - r4;                        \
                    if (PP == 1) { a1x -= ux; a1y -= uy; a2x -= tx;          \
                                   a2y -= ty; a3x += ux; a3y += uy; }        \
                    if (PP == 3) { a1x += ux; a1y += uy; a2x -= tx;          \
                                   a2y -= ty; a3x -= ux; a3y -= uy; }        \
                }                                                            \
                float ex = E.x * S.x - E.y * S.y;                            \
                E.y = E.x * S.y + E.y * S.x;                                 \
                E.x = ex;                                                    \
                ++nt;                                                        \
            }
#pragma unroll
            for (int g4 = 0; g4 < 3; ++g4) {
                S2P(1) S2P(2) S2P(3) S2P(0)
            }
            S2P(1) S2P(2) S2P(3)
#undef S2P
            s_g[m * 32 + q0]      = make_float2(a0x, a0y);
            s_g[m * 32 + q0 + 8]  = make_float2(a1x, a1y);
            s_g[m * 32 + q0 + 16] = make_float2(a2x, a2y);
            s_g[m * 32 + q0 + 24] = make_float2(a3x, a3y);
        }
        __syncthreads();

        // pass B: pair g over mt
        for (int i = tid; i < 480; i += 256) {
            int mt = 1 + (i >> 5), q = i & 31;
            float2 gp = s_g[(15 + mt) * 32 + q];
            float2 gm = s_g[(15 - mt) * 32 + q];
            sp3[(mt - 1) * 32 + q] = make_float2(gp.x + gm.x, gp.y - gm.y);
        }
        __syncthreads();

        // step 3 + in-warp pass C
        {
            int q = tid & 31, p0 = tid >> 5;
            float2 S, E;
            __sincosf((float)p0 * TWOPI_32F, &S.y, &S.x);
            E = S;
            float c = s_g[15 * 32 + q].x;
            float a0 = c, a1 = c, a2 = c, a3 = c;
            const float2* pcol = sp3 + q;
            int mt = 1;
#define S3P(PP)                                                              \
            {                                                                \
                float2 v = pcol[(mt - 1) * 32];                              \
                float u1 = E.x * v.x, u2 = E.y * v.y;                        \
                float tx = u1 - u2;                                          \
                a0 += tx;                                                    \
                if (PP == 0) { a1 += tx; a2 += tx; a3 += tx; }               \
                if (PP == 2) { a1 -= tx; a2 += tx; a3 -= tx; }               \
                if (PP == 1 || PP == 3) {                                    \
                    float v1 = E.y * v.x, v2 = E.x * v.y;                    \
                    float ux = v1 + v2;                                      \
                    if (PP == 1) { a1 -= ux; a2 -= tx; a3 += ux; }           \
                    if (PP == 3) { a1 += ux; a2 -= tx; a3 -= ux; }           \
                }                                                            \
                float ex = E.x * S.x - E.y * S.y;                            \
                E.y = E.x * S.y + E.y * S.x;                                 \
                E.x = ex;                                                    \
                ++mt;                                                        \
            }
#pragma unroll
            for (int g4 = 0; g4 < 3; ++g4) {
                S3P(1) S3P(2) S3P(3) S3P(0)
            }
            S3P(1) S3P(2) S3P(3)
#undef S3P
            a0 = fmaxf(a0, 0.f);
            a1 = fmaxf(a1, 0.f);
            a2 = fmaxf(a2, 0.f);
            a3 = fmaxf(a3, 0.f);
            int src = (32 - q) & 31;
            float b0 = __shfl_sync(0xffffffffu, a0, src);
            float b1 = __shfl_sync(0xffffffffu, a1, src);
            float b2 = __shfl_sync(0xffffffffu, a2, src);
            float b3 = __shfl_sync(0xffffffffu, a3, src);
            __syncthreads();
            if (q >= 1 && q <= 15) {
                int qm1 = q - 1;
                sp4[p0 * 17 + qm1]        = make_float2(a0 + b0, a0 - b0);
                sp4[(p0 + 8) * 17 + qm1]  = make_float2(a1 + b1, a1 - b1);
                sp4[(p0 + 16) * 17 + qm1] = make_float2(a2 + b2, a2 - b2);
                sp4[(p0 + 24) * 17 + qm1] = make_float2(a3 + b3, a3 - b3);
            } else if (q == 0) {
                s_r016[p0]      = a0;
                s_r016[p0 + 8]  = a1;
                s_r016[p0 + 16] = a2;
                s_r016[p0 + 24] = a3;
            } else if (q == 16) {
                s_r016[32 + p0]      = a0;
                s_r016[32 + p0 + 8]  = a1;
                s_r016[32 + p0 + 16] = a2;
                s_r016[32 + p0 + 24] = a3;
            }
        }
        __syncthreads();

        // step 4
        {
            int p = tid >> 3, d = tid & 7;
            float2 W1;
            __sincosf((float)d * TWOPI_32F, &W1.y, &W1.x);
            W1.y = -W1.y;
            float2 W = W1;
            float r0 = s_r016[p];
            float r16 = s_r016[32 + p];
            float axv = r0 + ((d & 1) ? -r16 : r16);
            float ayv = 0.f;
            const float2* sd = sp4 + p * 17;
#pragma unroll
            for (int q = 1; q <= 15; ++q) {
                float2 v = sd[q - 1];
                axv += v.x * W.x;
                ayv += v.y * W.y;
                float wx = W.x * W1.x - W.y * W1.y;
                W.y = W.x * W1.y + W.y * W1.x;
                W.x = wx;
            }
            s_u[p * 8 + d] = make_float2(axv, ayv);
        }
        __syncthreads();

        // step 5 (Hermitian half)
        if (tid < 120) {
            int m2 = tid >> 3, d = tid & 7;
            int n2 = 7 + d;
            int mt = m2 - 7;
            float2 W = make_float2(1.f, 0.f), S5;
            {
                float ss, cc;
                __sincosf((float)mt * TWOPI_32F, &ss, &cc);
                S5 = make_float2(cc, -ss);
            }
            float axv = 0.f, ayv = 0.f;
            const float2* ucol = s_u + d;
#pragma unroll
            for (int p = 0; p < 32; ++p) {
                float2 u = ucol[p * 8];
                axv += u.x * W.x - u.y * W.y;
                ayv += u.x * W.y + u.y * W.x;
                float wx = W.x * S5.x - W.y * S5.y;
                W.y = W.x * S5.y + W.y * S5.x;
                W.x = wx;
            }
            size_t plane = (size_t)(2 * bp + bb) * 1024 + f * 32 + j;
            float2* outp = g_xmn + plane * 225;
            outp[m2 * 15 + n2] = make_float2(axv, ayv);
            if (d > 0)
                outp[(14 - m2) * 15 + (14 - n2)] = make_float2(axv, -ayv);
        }
        __syncthreads();
    }
}

// ------------------------- k_G: xmn -> xh2 -> G (per (b,c)) ----------------
__global__ __launch_bounds__(512) void k_G() {
    __shared__ float2 s_xh2[2 * 8 * 225];
    __shared__ float  s_d2i0[1800];
    int bc = blockIdx.x;
    int tid = threadIdx.x;  // 512

    for (int i = tid; i < 1800; i += 512) s_d2i0[i] = g_D2I0[i];

    if (tid < 450) {
        int jh = tid / 225, mk = tid % 225;
        float2 acc[8];
#pragma unroll
        for (int l = 0; l < 8; ++l) acc[l] = make_float2(0.f, 0.f);
        const float2* xp = g_xmn + (size_t)bc * 7200 + jh * 16 * 225 + mk;
        const float* dp = g_D2F + jh * 16 * 225 + mk;
#pragma unroll 4
        for (int j = 0; j < 16; ++j) {
            float2 xv = xp[j * 225];
#pragma unroll
            for (int l = 0; l < 8; ++l) {
                float d = dp[l * 7200 + j * 225];
                acc[l].x += d * xv.x;
                acc[l].y += d * xv.y;
            }
        }
#pragma unroll
        for (int l = 0; l < 8; ++l)
            s_xh2[jh * 1800 + l * 225 + mk] = acc[l];
    }
    __syncthreads();

    for (int i = tid; i < 1800; i += 512) {
        float2 a = s_xh2[i], b = s_xh2[1800 + i];
        s_xh2[i] = make_float2(a.x + b.x, a.y + b.y);
    }
    __syncthreads();

    float2* gout = g_G + (size_t)bc * 1800;
    for (int idx = tid; idx < 1800; idx += 512) {
        int l = idx / 225, nk = idx % 225;
        int n = nk / 15, k = nk % 15;
        float ax = 0.f, ay = 0.f;
        if (abs(n - 7) <= l) {
            const float* dp = s_d2i0 + l * 225 + n;
            const float2* xp = s_xh2 + l * 225 + k;
            for (int m = 7 - l; m <= 7 + l; ++m) {
                float d = dp[m * 15];
                float2 v = xp[m * 15];
                ax += d * v.x;
                ay += d * v.y;
            }
        }
        gout[idx] = make_float2(ax, ay);
    }
}

// ------------------------- k_dot: i-outer, fl-inner (G read once) ----------
// Block (c, ft) = 256 blocks x 512 threads; warp = batch b. G chunk loaded
// once per i-iter and reused for all 8 fl; w2 streamed exactly once.
__global__ __launch_bounds__(512) void k_dot(const float* __restrict__ w2r,
                                             const float* __restrict__ w2i) {
    int c  = blockIdx.x;      // 32
    int ft = blockIdx.y;      // 8
    int tid = threadIdx.x;    // 512
    int b = tid >> 5;         // warp = batch 0..15
    int lane = tid & 31;

    const float4* X4 = (const float4*)(g_G + ((size_t)b * 32 + c) * 1800);
    const float4* Wr4 = (const float4*)(w2r + ((size_t)c * 64 + ft * 8) * 1800);
    const float4* Wi4 = (const float4*)(w2i + ((size_t)c * 64 + ft * 8) * 1800);

    float acc[8] = {0.f, 0.f, 0.f, 0.f, 0.f, 0.f, 0.f, 0.f};
    for (int i = lane; i < 450; i += 32) {
        float4 g0 = X4[2 * i], g1 = X4[2 * i + 1];
#pragma unroll
        for (int fl = 0; fl < 8; ++fl) {
            float4 wr = Wr4[fl * 450 + i];
            float4 wi = Wi4[fl * 450 + i];
            acc[fl] += g0.x * wr.x + g0.y * wi.x + g0.z * wr.y + g0.w * wi.y
                     + g1.x * wr.z + g1.y * wi.z + g1.z * wr.w + g1.w * wi.w;
        }
    }
#pragma unroll
    for (int fl = 0; fl < 8; ++fl) {
        float a = acc[fl];
#pragma unroll
        for (int o = 16; o > 0; o >>= 1)
            a += __shfl_xor_sync(0xffffffffu, a, o);
        if (lane == 0)
            g_partial[(c * 8 + ft) * 128 + b * 8 + fl] = a;
    }
}

// ------------------------- head: reduce + conv1d + BN + FC -----------------
__global__ void k_head(const float* __restrict__ w3, const float* __restrict__ b3,
                       const float* __restrict__ gam, const float* __restrict__ bet,
                       const float* __restrict__ fcw, const float* __restrict__ fcb,
                       float* __restrict__ out) {
    __shared__ float s_feat[16 * 64];
    __shared__ float s_r3[16 * 570];
    __shared__ float s_mu[10], s_rstd[10];
    __shared__ float s_ps[160], s_ps2[160];
    int tid = threadIdx.x;    // 256

    for (int idx = tid; idx < 1024; idx += 256) {
        int b = idx >> 6;
        int f = idx & 63;
        int ft = f >> 3, fl = f & 7;
        float s = 0.f;
#pragma unroll
        for (int c = 0; c < 32; ++c)
            s += g_partial[(c * 8 + ft) * 128 + (b << 3) + fl];
        s_feat[b * 64 + f] = fmaxf(s, 0.f);
    }
    __syncthreads();

    for (int idx = tid; idx < 9120; idx += 256) {
        int b = idx / 570;
        int r = idx % 570;
        int o = r / 57, t = r % 57;
        float s = b3[o];
#pragma unroll
        for (int k = 0; k < 8; ++k)
            s += w3[o * 8 + k] * s_feat[b * 64 + t + k];
        s_r3[idx] = fmaxf(s, 0.f);
    }
    __syncthreads();

    if (tid < 160) {
        int o = tid >> 4, i = tid & 15;
        float s = 0.f, s2 = 0.f;
        for (int idx2 = i; idx2 < 912; idx2 += 16) {
            int b = idx2 / 57, t = idx2 % 57;
            float v = s_r3[b * 570 + o * 57 + t];
            s += v;
            s2 += v * v;
        }
        s_ps[tid] = s;
        s_ps2[tid] = s2;
    }
    __syncthreads();

    if (tid < 10) {
        float s = 0.f, s2 = 0.f;
#pragma unroll
        for (int i = 0; i < 16; ++i) {
            s += s_ps[tid * 16 + i];
            s2 += s_ps2[tid * 16 + i];
        }
        float mu = s / 912.f;
        float var = s2 / 912.f - mu * mu;
        s_mu[tid] = mu;
        s_rstd[tid] = rsqrtf(var + 1e-5f);
    }
    __syncthreads();

    for (int idx = tid; idx < 9120; idx += 256) {
        int o = (idx % 570) / 57;
        s_r3[idx] = gam[o] * (s_r3[idx] - s_mu[o]) * s_rstd[o] + bet[o];
    }
    __syncthreads();

    if (tid < 160) {
        int b = tid / 10, i = tid % 10;
        float s = fcb[i];
        const float* wr = fcw + i * 570;
        const float* xr = s_r3 + b * 570;
        for (int z = 0; z < 570; ++z) s += xr[z] * wr[z];
        out[b * 10 + i] = s;
    }
}

// ---------------------------------------------------------------------------
extern "C" void kernel_launch(void* const* d_in, const int* in_sizes, int n_in,
                              void* d_out, int out_size) {
    const float* x   = (const float*)d_in[0];
    const float* w1r = (const float*)d_in[1];
    const float* w1i = (const float*)d_in[2];
    const float* w2r = (const float*)d_in[3];
    const float* w2i = (const float*)d_in[4];
    const float* c3w = (const float*)d_in[5];
    const float* c3b = (const float*)d_in[6];
    const float* bng = (const float*)d_in[7];
    const float* bnb = (const float*)d_in[8];
    const float* fcw = (const float*)d_in[9];
    const float* fcb = (const float*)d_in[10];
    float* out = (float*)d_out;

    t_setup<<<1, 64>>>();
    t_tables<<<(653448 + 127) / 128, 128>>>();

    k_xh<<<124, dim3(64, 4)>>>(x);
    k_main<<<8 * 32 * 32, 256>>>(w1r, w1i);
    k_G<<<512, 512>>>();
    k_dot<<<dim3(32, 8), 512>>>(w2r, w2i);
    k_head<<<1, 256>>>(c3w, c3b, bng, bnb, fcw, fcb, out);
}